// round 7
// baseline (speedup 1.0000x reference)
#include <cuda_runtime.h>
#include <cmath>
#include <cstdint>

#define BSZ   2048          // B_DAYS * STOCKS
#define TT    60
#define HID   256
#define G3    768           // 3*HID
#define DF    6
#define NSAMP 20480         // 4 * K_DAY * STOCKS
#define NDAYS 240
#define KDAY  10
#define NNB   10

// ---------------- device scratch (no allocations allowed) ----------------
__device__ float g_h[BSZ * HID];
__device__ float g_hs[BSZ * TT * HID];        // layer-0 hidden sequence
__device__ float g_xw1[(size_t)BSZ * TT * G3];// layer-1 input gates
__device__ float g_bias1[G3];                 // combined b_ih1 (+ b_hh1 for r,z)
__device__ float g_mb1[BSZ * 512];
__device__ float g_mb2[BSZ * 512];
__device__ float g_mb[BSZ * HID];
__device__ float g_mbday[4 * HID];
__device__ int   g_dayidx[4 * KDAY];
__device__ int   g_rowmap[NSAMP];
__device__ float g_kh[NSAMP * HID];
__device__ float g_khn[NSAMP];
__device__ float g_q[BSZ * HID];
__device__ float g_qn[BSZ];
__device__ float g_cs[(size_t)BSZ * NSAMP];
__device__ float g_vals[BSZ * NNB];
__device__ int   g_nidx[BSZ * NNB];

// ---------------- tf32 helpers ----------------
__device__ __forceinline__ void split_tf32(float x, uint32_t& hi, uint32_t& lo)
{
    uint32_t h;
    asm("cvt.rna.tf32.f32 %0, %1;" : "=r"(h) : "f"(x));
    float rem = x - __uint_as_float(h);
    uint32_t l;
    asm("cvt.rna.tf32.f32 %0, %1;" : "=r"(l) : "f"(rem));
    hi = h; lo = l;
}

__device__ __forceinline__ void mma_tf32(float* d, const uint32_t* a, const uint32_t* b)
{
    asm volatile(
        "mma.sync.aligned.m16n8k8.row.col.f32.tf32.tf32.f32 "
        "{%0,%1,%2,%3}, {%4,%5,%6,%7}, {%8,%9}, {%0,%1,%2,%3};"
        : "+f"(d[0]), "+f"(d[1]), "+f"(d[2]), "+f"(d[3])
        : "r"(a[0]), "r"(a[1]), "r"(a[2]), "r"(a[3]), "r"(b[0]), "r"(b[1]));
}

__device__ __forceinline__ float sigmoidf_(float x) { return 1.f / (1.f + expf(-x)); }

#define CP_ASYNC16(dst, src) \
    asm volatile("cp.async.cg.shared.global [%0], [%1], 16;\n" :: "r"(dst), "l"(src))
#define CP_COMMIT()  asm volatile("cp.async.commit_group;\n")
#define CP_WAIT1()   asm volatile("cp.async.wait_group 1;\n")
#define CP_WAIT0()   asm volatile("cp.async.wait_group 0;\n")

// ---------------- 3xTF32 tensor-core GEMM: C[M,N] = A[M,K] @ B[N,K]^T + bias ----
// act: 0 none, 1 leaky(0.01), 2 cosine-normalize by rnorm[m]*cnorm[n]
#define XBM 128
#define XBN 64
#define XBK 32
#define XPAD 36

__global__ void gemm_x(const float* __restrict__ A, const float* __restrict__ B,
                       const float* __restrict__ bias, float* __restrict__ C,
                       int M, int N, int K, int act,
                       const int* __restrict__ rowmap,
                       const float* __restrict__ rnorm, const float* __restrict__ cnorm)
{
    __shared__ float As[XBM][XPAD];   // [m][k]
    __shared__ float Bs[XBN][XPAD];   // [n][k]
    const int bm = blockIdx.y * XBM;
    const int bn = blockIdx.x * XBN;
    const int tid = threadIdx.x;                 // 256
    const int warp = tid >> 5, lane = tid & 31;
    const int wm = (warp & 3) * 32;
    const int wn = (warp >> 2) * 32;
    const int g = lane >> 2, tg = lane & 3;

    float acc[2][4][4];
    #pragma unroll
    for (int a = 0; a < 2; a++)
        #pragma unroll
        for (int b = 0; b < 4; b++)
            #pragma unroll
            for (int c = 0; c < 4; c++) acc[a][b][c] = 0.f;

    for (int k0 = 0; k0 < K; k0 += XBK) {
        #pragma unroll
        for (int i = 0; i < 4; i++) {
            int idx = tid + i * 256;                   // 0..1023
            int r = idx >> 3, c4 = (idx & 7) * 4;
            int arow = bm + r;
            if (rowmap) arow = rowmap[arow];
            float4 v = *(const float4*)(A + (size_t)arow * K + k0 + c4);
            As[r][c4 + 0] = v.x; As[r][c4 + 1] = v.y;
            As[r][c4 + 2] = v.z; As[r][c4 + 3] = v.w;
        }
        #pragma unroll
        for (int i = 0; i < 2; i++) {
            int idx = tid + i * 256;                   // 0..511
            int r = idx >> 3, c4 = (idx & 7) * 4;
            float4 v = *(const float4*)(B + (size_t)(bn + r) * K + k0 + c4);
            Bs[r][c4 + 0] = v.x; Bs[r][c4 + 1] = v.y;
            Bs[r][c4 + 2] = v.z; Bs[r][c4 + 3] = v.w;
        }
        __syncthreads();
        #pragma unroll
        for (int kc = 0; kc < 4; kc++) {
            const int kb = kc * 8;
            uint32_t ahi[2][4], alo[2][4];
            #pragma unroll
            for (int mt = 0; mt < 2; mt++) {
                const int r0 = wm + mt * 16;
                split_tf32(As[r0 + g][kb + tg],         ahi[mt][0], alo[mt][0]);
                split_tf32(As[r0 + g + 8][kb + tg],     ahi[mt][1], alo[mt][1]);
                split_tf32(As[r0 + g][kb + tg + 4],     ahi[mt][2], alo[mt][2]);
                split_tf32(As[r0 + g + 8][kb + tg + 4], ahi[mt][3], alo[mt][3]);
            }
            uint32_t bhi[4][2], blo[4][2];
            #pragma unroll
            for (int nt = 0; nt < 4; nt++) {
                const int c0 = wn + nt * 8;
                split_tf32(Bs[c0 + g][kb + tg],     bhi[nt][0], blo[nt][0]);
                split_tf32(Bs[c0 + g][kb + tg + 4], bhi[nt][1], blo[nt][1]);
            }
            #pragma unroll
            for (int mt = 0; mt < 2; mt++)
                #pragma unroll
                for (int nt = 0; nt < 4; nt++) {
                    mma_tf32(acc[mt][nt], alo[mt], bhi[nt]);
                    mma_tf32(acc[mt][nt], ahi[mt], blo[nt]);
                    mma_tf32(acc[mt][nt], ahi[mt], bhi[nt]);
                }
        }
        __syncthreads();
    }

    #pragma unroll
    for (int mt = 0; mt < 2; mt++) {
        #pragma unroll
        for (int nt = 0; nt < 4; nt++) {
            const int r0 = bm + wm + mt * 16 + g;
            const int c0 = bn + wn + nt * 8 + tg * 2;
            #pragma unroll
            for (int ci = 0; ci < 4; ci++) {
                const int m = r0 + ((ci >> 1) ? 8 : 0);
                const int nn = c0 + (ci & 1);
                float v = acc[mt][nt][ci];
                if (bias) v += bias[nn];
                if (act == 1) {
                    v = (v >= 0.f) ? v : 0.01f * v;
                } else if (act == 2) {
                    float den = rnorm[m] * cnorm[nn];
                    v = (den != 0.f) ? v / den : 0.f;
                }
                C[(size_t)m * N + nn] = v;
            }
        }
    }
}

// ---------------- persistent GRU kernels ----------------
// grid 128 CTAs x 256 threads; 16 rows/CTA; all 60 timesteps internal.
// Whh streamed per step in 64-gate chunks (12 chunks), cp.async double-buffered.
// h + tf32 hi/lo split resident in smem. 3xTF32 mma, fused gate epilogue.
#define GROWS 16
#define GCH   64       // gates per chunk
#define NCH   12       // chunks per step (768/64)
#define BPAD  260
#define HPAD  260

#define SMEM_BS   (2 * GCH * BPAD)                 // floats
#define SMEM_H    (GROWS * HPAD)
#define SMEM1_FLT (SMEM_BS + 3 * SMEM_H + 256)
#define SMEM0_FLT (SMEM1_FLT + 3 * 256 + G3 * DF + GROWS * DF)

__device__ __forceinline__ void cp_chunk(const float* __restrict__ Whh, float* Bs,
                                         int chunk, int buf, int tid)
{
    const float* src = Whh + (size_t)chunk * GCH * HID;
    float* dstbase = Bs + buf * GCH * BPAD;
    #pragma unroll
    for (int j = 0; j < 16; j++) {
        int idx = tid + j * 256;          // float4 id, 0..4095
        int gate = idx >> 6, c4 = idx & 63;
        uint32_t d = (uint32_t)__cvta_generic_to_shared(dstbase + gate * BPAD + c4 * 4);
        CP_ASYNC16(d, src + (size_t)idx * 4);
    }
    CP_COMMIT();
}

// core mainloop shared by both layers via a macro-free pattern: duplicated code.
__global__ void __launch_bounds__(256) gru_persist0(
    const float* __restrict__ inp, const float* __restrict__ Whh,
    const float* __restrict__ bhh, const float* __restrict__ Wih,
    const float* __restrict__ bih, float* __restrict__ hs_out)
{
    extern __shared__ float sm[];
    float* Bs  = sm;
    float* Hr  = Bs + SMEM_BS;
    float* Hh  = Hr + SMEM_H;
    float* Hl  = Hh + SMEM_H;
    float* bn_ = Hl + SMEM_H;          // bhh_n [256]
    float* br_ = bn_ + 256;            // bih_r + bhh_r
    float* bz_ = br_ + 256;            // bih_z + bhh_z
    float* bx_ = bz_ + 256;            // bih_n
    float* Wih_s = bx_ + 256;          // [768][6]
    float* xs  = Wih_s + G3 * DF;      // [16][6]

    const int tid = threadIdx.x;
    const int warp = tid >> 5, lane = tid & 31;
    const int g = lane >> 2, tg = lane & 3;
    const int row0 = blockIdx.x * GROWS;

    for (int i = tid; i < SMEM_H; i += 256) { Hr[i] = 0.f; Hh[i] = 0.f; Hl[i] = 0.f; }
    if (tid < 256) {
        bn_[tid] = bhh[512 + tid];
        br_[tid] = bih[tid] + bhh[tid];
        bz_[tid] = bih[256 + tid] + bhh[256 + tid];
        bx_[tid] = bih[512 + tid];
    }
    for (int i = tid; i < G3 * DF; i += 256) Wih_s[i] = Wih[i];
    __syncthreads();

    cp_chunk(Whh, Bs, 0, 0, tid);

    float acc[NCH][4];
    #pragma unroll
    for (int c = 0; c < NCH; c++)
        #pragma unroll
        for (int e = 0; e < 4; e++) acc[c][e] = 0.f;

    for (int t = 0; t < TT; t++) {
        #pragma unroll
        for (int c = 0; c < NCH; c++) {
            const bool pf = !(t == TT - 1 && c == NCH - 1);
            if (pf) cp_chunk(Whh, Bs, (c + 1) % NCH, (c + 1) & 1, tid);
            if (c == 0 && tid < GROWS * DF)
                xs[tid] = inp[(row0 + tid / DF) * (DF * TT) + (tid % DF) * TT + t];
            if (pf) CP_WAIT1(); else CP_WAIT0();
            __syncthreads();
            const float* Bw = Bs + (c & 1) * GCH * BPAD + (warp * 8) * BPAD;
            #pragma unroll 8
            for (int kb = 0; kb < HID; kb += 8) {
                uint32_t ah[4], al[4];
                ah[0] = __float_as_uint(Hh[g * HPAD + kb + tg]);
                al[0] = __float_as_uint(Hl[g * HPAD + kb + tg]);
                ah[1] = __float_as_uint(Hh[(g + 8) * HPAD + kb + tg]);
                al[1] = __float_as_uint(Hl[(g + 8) * HPAD + kb + tg]);
                ah[2] = __float_as_uint(Hh[g * HPAD + kb + tg + 4]);
                al[2] = __float_as_uint(Hl[g * HPAD + kb + tg + 4]);
                ah[3] = __float_as_uint(Hh[(g + 8) * HPAD + kb + tg + 4]);
                al[3] = __float_as_uint(Hl[(g + 8) * HPAD + kb + tg + 4]);
                float b0 = Bw[g * BPAD + kb + tg];
                float b1 = Bw[g * BPAD + kb + tg + 4];
                uint32_t bh[2], bl[2];
                split_tf32(b0, bh[0], bl[0]);
                split_tf32(b1, bh[1], bl[1]);
                mma_tf32(acc[c], al, bh);
                mma_tf32(acc[c], ah, bl);
                mma_tf32(acc[c], ah, bh);
            }
            __syncthreads();
        }
        // epilogue: warp owns cols {c*64 + warp*8 + tg*2 + {0,1}} for c in 0..3
        #pragma unroll
        for (int c = 0; c < 4; c++) {
            const int colb = c * 64 + warp * 8 + tg * 2;
            #pragma unroll
            for (int e = 0; e < 4; e++) {
                const int row = g + ((e >> 1) ? 8 : 0);
                const int col = colb + (e & 1);
                float xr = br_[col], xz = bz_[col], xn = bx_[col];
                const float* wr = Wih_s + col * DF;
                const float* wz = Wih_s + (256 + col) * DF;
                const float* wn = Wih_s + (512 + col) * DF;
                #pragma unroll
                for (int f = 0; f < DF; f++) {
                    const float xv = xs[row * DF + f];
                    xr += xv * wr[f]; xz += xv * wz[f]; xn += xv * wn[f];
                }
                const float r  = sigmoidf_(xr + acc[c][e]);
                const float z  = sigmoidf_(xz + acc[c + 4][e]);
                const float nn = tanhf(xn + r * (acc[c + 8][e] + bn_[col]));
                const float hold = Hr[row * HPAD + col];
                const float hv = (1.f - z) * nn + z * hold;
                Hr[row * HPAD + col] = hv;
                uint32_t hi, lo; split_tf32(hv, hi, lo);
                Hh[row * HPAD + col] = __uint_as_float(hi);
                Hl[row * HPAD + col] = __uint_as_float(lo);
                hs_out[((size_t)(row0 + row) * TT + t) * HID + col] = hv;
            }
        }
        #pragma unroll
        for (int c = 0; c < NCH; c++)
            #pragma unroll
            for (int e = 0; e < 4; e++) acc[c][e] = 0.f;
        __syncthreads();
    }
}

__global__ void __launch_bounds__(256) gru_persist1(
    const float* __restrict__ xw, const float* __restrict__ Whh,
    const float* __restrict__ bhh, float* __restrict__ hfinal)
{
    extern __shared__ float sm[];
    float* Bs  = sm;
    float* Hr  = Bs + SMEM_BS;
    float* Hh  = Hr + SMEM_H;
    float* Hl  = Hh + SMEM_H;
    float* bn_ = Hl + SMEM_H;          // bhh_n [256]

    const int tid = threadIdx.x;
    const int warp = tid >> 5, lane = tid & 31;
    const int g = lane >> 2, tg = lane & 3;
    const int row0 = blockIdx.x * GROWS;

    for (int i = tid; i < SMEM_H; i += 256) { Hr[i] = 0.f; Hh[i] = 0.f; Hl[i] = 0.f; }
    if (tid < 256) bn_[tid] = bhh[512 + tid];
    __syncthreads();

    cp_chunk(Whh, Bs, 0, 0, tid);

    float acc[NCH][4];
    #pragma unroll
    for (int c = 0; c < NCH; c++)
        #pragma unroll
        for (int e = 0; e < 4; e++) acc[c][e] = 0.f;

    for (int t = 0; t < TT; t++) {
        #pragma unroll
        for (int c = 0; c < NCH; c++) {
            const bool pf = !(t == TT - 1 && c == NCH - 1);
            if (pf) cp_chunk(Whh, Bs, (c + 1) % NCH, (c + 1) & 1, tid);
            if (pf) CP_WAIT1(); else CP_WAIT0();
            __syncthreads();
            const float* Bw = Bs + (c & 1) * GCH * BPAD + (warp * 8) * BPAD;
            #pragma unroll 8
            for (int kb = 0; kb < HID; kb += 8) {
                uint32_t ah[4], al[4];
                ah[0] = __float_as_uint(Hh[g * HPAD + kb + tg]);
                al[0] = __float_as_uint(Hl[g * HPAD + kb + tg]);
                ah[1] = __float_as_uint(Hh[(g + 8) * HPAD + kb + tg]);
                al[1] = __float_as_uint(Hl[(g + 8) * HPAD + kb + tg]);
                ah[2] = __float_as_uint(Hh[g * HPAD + kb + tg + 4]);
                al[2] = __float_as_uint(Hl[g * HPAD + kb + tg + 4]);
                ah[3] = __float_as_uint(Hh[(g + 8) * HPAD + kb + tg + 4]);
                al[3] = __float_as_uint(Hl[(g + 8) * HPAD + kb + tg + 4]);
                float b0 = Bw[g * BPAD + kb + tg];
                float b1 = Bw[g * BPAD + kb + tg + 4];
                uint32_t bh[2], bl[2];
                split_tf32(b0, bh[0], bl[0]);
                split_tf32(b1, bh[1], bl[1]);
                mma_tf32(acc[c], al, bh);
                mma_tf32(acc[c], ah, bl);
                mma_tf32(acc[c], ah, bh);
            }
            __syncthreads();
        }
        #pragma unroll
        for (int c = 0; c < 4; c++) {
            const int colb = c * 64 + warp * 8 + tg * 2;
            #pragma unroll
            for (int e = 0; e < 4; e++) {
                const int row = g + ((e >> 1) ? 8 : 0);
                const int col = colb + (e & 1);
                const size_t xb = ((size_t)(row0 + row) * TT + t) * G3 + col;
                const float xr = xw[xb];
                const float xz = xw[xb + 256];
                const float xn = xw[xb + 512];
                const float r  = sigmoidf_(xr + acc[c][e]);
                const float z  = sigmoidf_(xz + acc[c + 4][e]);
                const float nn = tanhf(xn + r * (acc[c + 8][e] + bn_[col]));
                const float hold = Hr[row * HPAD + col];
                const float hv = (1.f - z) * nn + z * hold;
                Hr[row * HPAD + col] = hv;
                uint32_t hi, lo; split_tf32(hv, hi, lo);
                Hh[row * HPAD + col] = __uint_as_float(hi);
                Hl[row * HPAD + col] = __uint_as_float(lo);
                if (t == TT - 1) hfinal[(size_t)(row0 + row) * HID + col] = hv;
            }
        }
        #pragma unroll
        for (int c = 0; c < NCH; c++)
            #pragma unroll
            for (int e = 0; e < 4; e++) acc[c][e] = 0.f;
        __syncthreads();
    }
}

// ---------------- small kernels ----------------
__global__ void bias_combine(const float* __restrict__ bih, const float* __restrict__ bhh,
                             float* __restrict__ out)
{
    const int i = blockIdx.x * 256 + threadIdx.x;
    if (i < G3) out[i] = bih[i] + ((i < 512) ? bhh[i] : 0.f);
}

__global__ void mb_day_mean()
{
    const int b = blockIdx.x, h = threadIdx.x;
    float s = 0.f;
    for (int st = 0; st < 512; st++) s += g_mb[(b * 512 + st) * HID + h];
    g_mbday[b * HID + h] = s * (1.f / 512.f);
}

__global__ void day_topk(const float* __restrict__ thd)
{
    const int b = blockIdx.x;
    const int d = threadIdx.x;
    __shared__ float sim[NDAYS];
    const float* mbd = g_mbday + b * HID;
    float xn = 0.f;
    for (int i = 0; i < HID; i++) { float v = mbd[i]; xn += v * v; }
    xn = sqrtf(xn);
    if (d < NDAYS) {
        const float* yr = thd + d * HID;
        float yn = 0.f, dot = 0.f;
        for (int i = 0; i < HID; i++) { float y = yr[i]; yn += y * y; dot += mbd[i] * y; }
        const float den = xn * sqrtf(yn);
        sim[d] = (den != 0.f) ? dot / den : 0.f;
    }
    __syncthreads();
    if (d == 0) {
        for (int kk = 0; kk < KDAY; kk++) {
            float best = -1e30f; int bi = 0;
            for (int q = 0; q < NDAYS; q++)
                if (sim[q] > best) { best = sim[q]; bi = q; }
            g_dayidx[b * KDAY + kk] = bi;
            sim[bi] = -1e30f;
        }
    }
}

__global__ void make_rowmap()
{
    const int m = blockIdx.x * 256 + threadIdx.x;
    if (m < NSAMP) g_rowmap[m] = g_dayidx[m >> 9] * 512 + (m & 511);
}

__global__ void rownorm256(const float* __restrict__ X, float* __restrict__ out, int R)
{
    const int warp = (blockIdx.x * blockDim.x + threadIdx.x) >> 5;
    const int lane = threadIdx.x & 31;
    if (warp >= R) return;
    const float* r = X + (size_t)warp * HID;
    float s = 0.f;
    for (int i = lane; i < HID; i += 32) { float v = r[i]; s += v * v; }
    #pragma unroll
    for (int o = 16; o > 0; o >>= 1) s += __shfl_xor_sync(0xffffffffu, s, o);
    if (lane == 0) out[warp] = sqrtf(s);
}

__global__ void neigh_topk()
{
    const int n = blockIdx.x;
    const int tid = threadIdx.x;
    const float* row = g_cs + (size_t)n * NSAMP;

    float tv[NNB]; int ti[NNB];
    #pragma unroll
    for (int i = 0; i < NNB; i++) { tv[i] = -1e30f; ti[i] = 0x7fffffff; }

    for (int it = 0; it < NSAMP / 256; it++) {
        const int idx = tid + it * 256;
        const float v = row[idx];
        if (v > tv[NNB - 1]) {
            int p = NNB - 1;
            while (p > 0 && tv[p - 1] < v) { tv[p] = tv[p - 1]; ti[p] = ti[p - 1]; p--; }
            tv[p] = v; ti[p] = idx;
        }
    }

    __shared__ float sval[256 * NNB];
    __shared__ int   sidx[256 * NNB];
    __shared__ float rv[256];
    __shared__ int   rp[256];
    #pragma unroll
    for (int i = 0; i < NNB; i++) { sval[tid * NNB + i] = tv[i]; sidx[tid * NNB + i] = ti[i]; }
    __syncthreads();

    for (int kk = 0; kk < NNB; kk++) {
        float best = -1e30f; int bp = tid * NNB;
        #pragma unroll
        for (int i = 0; i < NNB; i++) {
            const float v = sval[tid * NNB + i];
            if (v > best) { best = v; bp = tid * NNB + i; }
        }
        rv[tid] = best; rp[tid] = bp;
        __syncthreads();
        for (int s = 128; s > 0; s >>= 1) {
            if (tid < s && rv[tid + s] > rv[tid]) { rv[tid] = rv[tid + s]; rp[tid] = rp[tid + s]; }
            __syncthreads();
        }
        if (tid == 0) {
            const int p = rp[0];
            g_vals[n * NNB + kk] = rv[0];
            g_nidx[n * NNB + kk] = sidx[p];
            sval[p] = -1e30f;
        }
        __syncthreads();
    }
}

__global__ void agg_fc(const float* __restrict__ fc_W, const float* __restrict__ fc_b,
                       float* __restrict__ y)
{
    const int n = blockIdx.x, h = threadIdx.x;
    float agg = 0.f;
    #pragma unroll
    for (int k = 0; k < NNB; k++) {
        const float v = g_vals[n * NNB + k] * (1.f / NNB);
        const int id = g_nidx[n * NNB + k];
        agg += v * g_kh[(size_t)id * HID + h];
    }
    float part = fc_W[h] * g_mb[n * HID + h] + fc_W[HID + h] * agg;
    __shared__ float red[256];
    red[h] = part;
    __syncthreads();
    for (int s = 128; s > 0; s >>= 1) {
        if (h < s) red[h] += red[h + s];
        __syncthreads();
    }
    if (h == 0) y[n] = red[0] + fc_b[0];
}

// ---------------- host ----------------
extern "C" void kernel_launch(void* const* d_in, const int* in_sizes, int n_in,
                              void* d_out, int out_size)
{
    const float* inp       = (const float*)d_in[0];
    const float* train_hid = (const float*)d_in[1];
    const float* thd       = (const float*)d_in[2];
    const float* W_ih0     = (const float*)d_in[3];
    const float* W_hh0     = (const float*)d_in[4];
    const float* b_ih0     = (const float*)d_in[5];
    const float* b_hh0     = (const float*)d_in[6];
    const float* W_ih1     = (const float*)d_in[7];
    const float* W_hh1     = (const float*)d_in[8];
    const float* b_ih1     = (const float*)d_in[9];
    const float* b_hh1     = (const float*)d_in[10];
    const float* lin0_W    = (const float*)d_in[11];
    const float* lin0_b    = (const float*)d_in[12];
    const float* lin1_W    = (const float*)d_in[13];
    const float* lin1_b    = (const float*)d_in[14];
    const float* lin2_W    = (const float*)d_in[15];
    const float* lin2_b    = (const float*)d_in[16];
    const float* proj1_W   = (const float*)d_in[17];
    const float* proj2_W   = (const float*)d_in[18];
    const float* fc_W      = (const float*)d_in[19];
    const float* fc_b      = (const float*)d_in[20];
    (void)in_sizes; (void)n_in; (void)out_size;

    float *p_h, *p_hs, *p_xw1, *p_bias1, *p_mb1, *p_mb2, *p_mb, *p_kh, *p_khn, *p_q, *p_qn, *p_cs;
    int *p_rowmap;
    cudaGetSymbolAddress((void**)&p_h, g_h);
    cudaGetSymbolAddress((void**)&p_hs, g_hs);
    cudaGetSymbolAddress((void**)&p_xw1, g_xw1);
    cudaGetSymbolAddress((void**)&p_bias1, g_bias1);
    cudaGetSymbolAddress((void**)&p_mb1, g_mb1);
    cudaGetSymbolAddress((void**)&p_mb2, g_mb2);
    cudaGetSymbolAddress((void**)&p_mb, g_mb);
    cudaGetSymbolAddress((void**)&p_kh, g_kh);
    cudaGetSymbolAddress((void**)&p_khn, g_khn);
    cudaGetSymbolAddress((void**)&p_q, g_q);
    cudaGetSymbolAddress((void**)&p_qn, g_qn);
    cudaGetSymbolAddress((void**)&p_cs, g_cs);
    cudaGetSymbolAddress((void**)&p_rowmap, g_rowmap);

    const int smem0 = SMEM0_FLT * 4;
    const int smem1 = SMEM1_FLT * 4;
    cudaFuncSetAttribute(gru_persist0, cudaFuncAttributeMaxDynamicSharedMemorySize, smem0);
    cudaFuncSetAttribute(gru_persist1, cudaFuncAttributeMaxDynamicSharedMemorySize, smem1);

    // ---- GRU layer 0: one persistent kernel, 60 steps internal ----
    gru_persist0<<<BSZ / GROWS, 256, smem0>>>(inp, W_hh0, b_hh0, W_ih0, b_ih0, p_hs);

    // ---- layer-1 input gates: one big 3xTF32 GEMM (combined bias) ----
    bias_combine<<<3, 256>>>(b_ih1, b_hh1, p_bias1);
    gemm_x<<<dim3(G3 / XBN, (BSZ * TT) / XBM), 256>>>(p_hs, W_ih1, p_bias1, p_xw1,
                                                      BSZ * TT, G3, HID, 0, nullptr, nullptr, nullptr);

    // ---- GRU layer 1: persistent ----
    gru_persist1<<<BSZ / GROWS, 256, smem1>>>(p_xw1, W_hh1, b_hh1, p_h);

    // ---- MLP (leaky relu) ----
    gemm_x<<<dim3(512 / XBN, BSZ / XBM), 256>>>(p_h, lin0_W, lin0_b, p_mb1,
                                                BSZ, 512, HID, 1, nullptr, nullptr, nullptr);
    gemm_x<<<dim3(512 / XBN, BSZ / XBM), 256>>>(p_mb1, lin1_W, lin1_b, p_mb2,
                                                BSZ, 512, 512, 1, nullptr, nullptr, nullptr);
    gemm_x<<<dim3(HID / XBN, BSZ / XBM), 256>>>(p_mb2, lin2_W, lin2_b, p_mb,
                                                BSZ, HID, 512, 1, nullptr, nullptr, nullptr);

    // ---- day similarity + gather ----
    mb_day_mean<<<4, HID>>>();
    day_topk<<<4, 256>>>(thd);
    make_rowmap<<<NSAMP / 256, 256>>>();
    gemm_x<<<dim3(HID / XBN, NSAMP / XBM), 256>>>(train_hid, proj2_W, nullptr, p_kh,
                                                  NSAMP, HID, HID, 0, p_rowmap, nullptr, nullptr);
    rownorm256<<<(NSAMP * 32) / 256, 256>>>(p_kh, p_khn, NSAMP);

    // ---- queries + cosine sim + neighbor aggregation ----
    gemm_x<<<dim3(HID / XBN, BSZ / XBM), 256>>>(p_mb, proj1_W, nullptr, p_q,
                                                BSZ, HID, HID, 0, nullptr, nullptr, nullptr);
    rownorm256<<<(BSZ * 32) / 256, 256>>>(p_q, p_qn, BSZ);
    gemm_x<<<dim3(NSAMP / XBN, BSZ / XBM), 256>>>(p_q, p_kh, nullptr, p_cs,
                                                  BSZ, NSAMP, HID, 2, nullptr, p_qn, p_khn);
    neigh_topk<<<BSZ, 256>>>();
    agg_fc<<<BSZ, 256>>>(fc_W, fc_b, (float*)d_out);
}

// round 8
// speedup vs baseline: 1.0969x; 1.0969x over previous
#include <cuda_runtime.h>
#include <cmath>
#include <cstdint>

#define BSZ   2048          // B_DAYS * STOCKS
#define TT    60
#define HID   256
#define G3    768           // 3*HID
#define DF    6
#define NSAMP 20480         // 4 * K_DAY * STOCKS
#define NDAYS 240
#define KDAY  10
#define NNB   10

// ---------------- device scratch (no allocations allowed) ----------------
__device__ float g_hp[2 * BSZ * HID];         // ping-pong h (raw)
__device__ int   g_bar[16];                   // per-row-slice barrier counters
__device__ float g_hs[BSZ * TT * HID];        // layer-0 hidden sequence
__device__ float g_xw1[(size_t)BSZ * TT * G3];// layer-1 input gates
__device__ float g_bias1[G3];                 // combined b_ih1 (+ b_hh1 for r,z)
__device__ float g_mb1[BSZ * 512];
__device__ float g_mb2[BSZ * 512];
__device__ float g_mb[BSZ * HID];
__device__ float g_mbday[4 * HID];
__device__ int   g_dayidx[4 * KDAY];
__device__ int   g_rowmap[NSAMP];
__device__ float g_kh[NSAMP * HID];
__device__ float g_khn[NSAMP];
__device__ float g_q[BSZ * HID];
__device__ float g_qn[BSZ];
__device__ float g_cs[(size_t)BSZ * NSAMP];
__device__ float g_vals[BSZ * NNB];
__device__ int   g_nidx[BSZ * NNB];

// ---------------- tf32 helpers ----------------
__device__ __forceinline__ void split_tf32(float x, uint32_t& hi, uint32_t& lo)
{
    uint32_t h;
    asm("cvt.rna.tf32.f32 %0, %1;" : "=r"(h) : "f"(x));
    float rem = x - __uint_as_float(h);
    uint32_t l;
    asm("cvt.rna.tf32.f32 %0, %1;" : "=r"(l) : "f"(rem));
    hi = h; lo = l;
}

__device__ __forceinline__ void mma_tf32(float* d, const uint32_t* a, const uint32_t* b)
{
    asm volatile(
        "mma.sync.aligned.m16n8k8.row.col.f32.tf32.tf32.f32 "
        "{%0,%1,%2,%3}, {%4,%5,%6,%7}, {%8,%9}, {%0,%1,%2,%3};"
        : "+f"(d[0]), "+f"(d[1]), "+f"(d[2]), "+f"(d[3])
        : "r"(a[0]), "r"(a[1]), "r"(a[2]), "r"(a[3]), "r"(b[0]), "r"(b[1]));
}

__device__ __forceinline__ float sigmoidf_(float x) { return 1.f / (1.f + expf(-x)); }

#define CP_ASYNC16(dst, src) \
    asm volatile("cp.async.cg.shared.global [%0], [%1], 16;\n" :: "r"(dst), "l"(src))
#define CP_COMMIT()  asm volatile("cp.async.commit_group;\n")
#define CP_WAIT1()   asm volatile("cp.async.wait_group 1;\n")
#define CP_WAIT0()   asm volatile("cp.async.wait_group 0;\n")

// ---------------- 3xTF32 tensor-core GEMM: C[M,N] = A[M,K] @ B[N,K]^T + bias ----
// act: 0 none, 1 leaky(0.01), 2 cosine-normalize by rnorm[m]*cnorm[n]
#define XBM 128
#define XBN 64
#define XBK 32
#define XPAD 36

__global__ void gemm_x(const float* __restrict__ A, const float* __restrict__ B,
                       const float* __restrict__ bias, float* __restrict__ C,
                       int M, int N, int K, int act,
                       const int* __restrict__ rowmap,
                       const float* __restrict__ rnorm, const float* __restrict__ cnorm)
{
    __shared__ float As[XBM][XPAD];   // [m][k]
    __shared__ float Bs[XBN][XPAD];   // [n][k]
    const int bm = blockIdx.y * XBM;
    const int bn = blockIdx.x * XBN;
    const int tid = threadIdx.x;                 // 256
    const int warp = tid >> 5, lane = tid & 31;
    const int wm = (warp & 3) * 32;
    const int wn = (warp >> 2) * 32;
    const int g = lane >> 2, tg = lane & 3;

    float acc[2][4][4];
    #pragma unroll
    for (int a = 0; a < 2; a++)
        #pragma unroll
        for (int b = 0; b < 4; b++)
            #pragma unroll
            for (int c = 0; c < 4; c++) acc[a][b][c] = 0.f;

    for (int k0 = 0; k0 < K; k0 += XBK) {
        #pragma unroll
        for (int i = 0; i < 4; i++) {
            int idx = tid + i * 256;                   // 0..1023
            int r = idx >> 3, c4 = (idx & 7) * 4;
            int arow = bm + r;
            if (rowmap) arow = rowmap[arow];
            float4 v = *(const float4*)(A + (size_t)arow * K + k0 + c4);
            As[r][c4 + 0] = v.x; As[r][c4 + 1] = v.y;
            As[r][c4 + 2] = v.z; As[r][c4 + 3] = v.w;
        }
        #pragma unroll
        for (int i = 0; i < 2; i++) {
            int idx = tid + i * 256;                   // 0..511
            int r = idx >> 3, c4 = (idx & 7) * 4;
            float4 v = *(const float4*)(B + (size_t)(bn + r) * K + k0 + c4);
            Bs[r][c4 + 0] = v.x; Bs[r][c4 + 1] = v.y;
            Bs[r][c4 + 2] = v.z; Bs[r][c4 + 3] = v.w;
        }
        __syncthreads();
        #pragma unroll
        for (int kc = 0; kc < 4; kc++) {
            const int kb = kc * 8;
            uint32_t ahi[2][4], alo[2][4];
            #pragma unroll
            for (int mt = 0; mt < 2; mt++) {
                const int r0 = wm + mt * 16;
                split_tf32(As[r0 + g][kb + tg],         ahi[mt][0], alo[mt][0]);
                split_tf32(As[r0 + g + 8][kb + tg],     ahi[mt][1], alo[mt][1]);
                split_tf32(As[r0 + g][kb + tg + 4],     ahi[mt][2], alo[mt][2]);
                split_tf32(As[r0 + g + 8][kb + tg + 4], ahi[mt][3], alo[mt][3]);
            }
            uint32_t bhi[4][2], blo[4][2];
            #pragma unroll
            for (int nt = 0; nt < 4; nt++) {
                const int c0 = wn + nt * 8;
                split_tf32(Bs[c0 + g][kb + tg],     bhi[nt][0], blo[nt][0]);
                split_tf32(Bs[c0 + g][kb + tg + 4], bhi[nt][1], blo[nt][1]);
            }
            #pragma unroll
            for (int mt = 0; mt < 2; mt++)
                #pragma unroll
                for (int nt = 0; nt < 4; nt++) {
                    mma_tf32(acc[mt][nt], alo[mt], bhi[nt]);
                    mma_tf32(acc[mt][nt], ahi[mt], blo[nt]);
                    mma_tf32(acc[mt][nt], ahi[mt], bhi[nt]);
                }
        }
        __syncthreads();
    }

    #pragma unroll
    for (int mt = 0; mt < 2; mt++) {
        #pragma unroll
        for (int nt = 0; nt < 4; nt++) {
            const int r0 = bm + wm + mt * 16 + g;
            const int c0 = bn + wn + nt * 8 + tg * 2;
            #pragma unroll
            for (int ci = 0; ci < 4; ci++) {
                const int m = r0 + ((ci >> 1) ? 8 : 0);
                const int nn = c0 + (ci & 1);
                float v = acc[mt][nt][ci];
                if (bias) v += bias[nn];
                if (act == 1) {
                    v = (v >= 0.f) ? v : 0.01f * v;
                } else if (act == 2) {
                    float den = rnorm[m] * cnorm[nn];
                    v = (den != 0.f) ? v / den : 0.f;
                }
                C[(size_t)m * N + nn] = v;
            }
        }
    }
}

// ---------------- persistent GRU v2: B resident, h streamed ----------------
// 128 CTAs = 8 col-slices x 16 row-slices. 384 threads (12 warps = 2m x 6n).
// Per CTA: 96-gate Whh slice resident in smem (raw, split on read); 128 rows,
// processed in 4 chunks of 32; h ping-pong in global, chunk-streamed cp.async.cg.
// Per-step inter-CTA sync: 16 groups of 8 CTAs via atomic counter (host-memset).
#define APAD 260
#define SM_B    (96 * APAD)
#define SM_A    (2 * 32 * APAD)
#define SM_C    (96 * 33)
#define SMP_FLT (SM_B + SM_A + SM_C + 96 + 32 + 96 * DF + 192)

__device__ __forceinline__ void cp_A(const float* __restrict__ hsrc, float* As,
                                     int rowbase, int buf, int tid)
{
    float* dst = As + buf * (32 * APAD);
    #pragma unroll
    for (int j = 0; j < 6; j++) {
        int idx = tid + j * 384;            // float4 index, 0..2047 valid
        if (idx < 2048) {
            int row = idx >> 6, c4 = (idx & 63) * 4;
            uint32_t d = (uint32_t)__cvta_generic_to_shared(dst + row * APAD + c4);
            CP_ASYNC16(d, hsrc + (size_t)(rowbase + row) * HID + c4);
        }
    }
    CP_COMMIT();
}

template<int LAYER>
__global__ void __launch_bounds__(384, 1) gru_pv2(
    const float* __restrict__ Whh, const float* __restrict__ bih,
    const float* __restrict__ bhh, const float* __restrict__ xin,
    const float* __restrict__ Wih, float* __restrict__ hpp,
    float* __restrict__ hs)
{
    extern __shared__ float sm[];
    float* Bs  = sm;                    // [96][APAD] raw Whh slice
    float* As  = Bs + SM_B;             // [2][32][APAD] h chunk stream
    float* Cst = As + SM_A;             // [96][33] acc staging
    float* b1  = Cst + SM_C;            // [96]
    float* bn2 = b1 + 96;               // [32]
    float* wih = bn2 + 32;              // [96][DF] (layer0)
    float* xs  = wih + 96 * DF;         // [32][DF] (layer0)

    const int tid = threadIdx.x;
    const int warp = tid >> 5, lane = tid & 31;
    const int mt = warp & 1, ng = warp >> 1;     // 2 m-tiles x 6 gate-16 slices
    const int g = lane >> 2, tg = lane & 3;
    const int bx = blockIdx.x & 7;               // col-slice
    const int rsl = blockIdx.x >> 3;             // row-slice
    const int row0 = rsl * 128;

    // resident Whh slice: local gate lg -> global row (lg/32)*256 + bx*32 + lg%32
    for (int i = tid; i < 96 * 64; i += 384) {   // float4 count
        int gate = i >> 6, c4 = (i & 63) * 4;
        int grow = (gate >> 5) * HID + bx * 32 + (gate & 31);
        *(float4*)&Bs[gate * APAD + c4] = *(const float4*)(Whh + (size_t)grow * HID + c4);
    }
    if (tid < 96) {
        int group = tid >> 5, col = bx * 32 + (tid & 31);
        float v = bih[group * HID + col];
        if (group < 2) v += bhh[group * HID + col];
        b1[tid] = v;
    }
    if (tid < 32) bn2[tid] = bhh[2 * HID + bx * 32 + tid];
    if (LAYER == 0) {
        for (int i = tid; i < 96 * DF; i += 384) {
            int lg = i / DF, f = i % DF;
            int grow = (lg >> 5) * HID + bx * 32 + (lg & 31);
            wih[i] = Wih[grow * DF + f];
        }
    }
    __syncthreads();

    cp_A(hpp, As, row0, 0, tid);    // step 0 reads parity-0 buffer (host-zeroed)

    for (int t = 0; t < TT; t++) {
        const float* hr = hpp + (size_t)(t & 1) * (BSZ * HID);
        float*       hw = hpp + (size_t)((t & 1) ^ 1) * (BSZ * HID);

        for (int c = 0; c < 4; c++) {
            if (c < 3) { cp_A(hr, As, row0 + (c + 1) * 32, (c + 1) & 1, tid); CP_WAIT1(); }
            else       { CP_WAIT0(); }
            __syncthreads();                       // A buf (c&1) ready

            float acc[2][4];
            #pragma unroll
            for (int nt = 0; nt < 2; nt++)
                #pragma unroll
                for (int e = 0; e < 4; e++) acc[nt][e] = 0.f;

            const float* Ab = As + (c & 1) * (32 * APAD) + (mt * 16) * APAD;
            #pragma unroll 8
            for (int kb = 0; kb < HID; kb += 8) {
                uint32_t ah[4], al[4];
                split_tf32(Ab[g * APAD + kb + tg],           ah[0], al[0]);
                split_tf32(Ab[(g + 8) * APAD + kb + tg],     ah[1], al[1]);
                split_tf32(Ab[g * APAD + kb + tg + 4],       ah[2], al[2]);
                split_tf32(Ab[(g + 8) * APAD + kb + tg + 4], ah[3], al[3]);
                #pragma unroll
                for (int nt = 0; nt < 2; nt++) {
                    const int n = ng * 16 + nt * 8 + g;
                    uint32_t bh[2], bl[2];
                    split_tf32(Bs[n * APAD + kb + tg],     bh[0], bl[0]);
                    split_tf32(Bs[n * APAD + kb + tg + 4], bh[1], bl[1]);
                    mma_tf32(acc[nt], al, bh);
                    mma_tf32(acc[nt], ah, bl);
                    mma_tf32(acc[nt], ah, bh);
                }
            }

            // stage acc -> Cst[gate][row]
            #pragma unroll
            for (int nt = 0; nt < 2; nt++)
                #pragma unroll
                for (int e = 0; e < 4; e++) {
                    int lg = ng * 16 + nt * 8 + tg * 2 + (e & 1);
                    int row = mt * 16 + g + ((e >> 1) ? 8 : 0);
                    Cst[lg * 33 + row] = acc[nt][e];
                }
            if (LAYER == 0 && tid < 32 * DF)
                xs[tid] = xin[(size_t)(row0 + c * 32 + tid / DF) * (DF * TT)
                              + (tid % DF) * TT + t];
            __syncthreads();                       // Cst + xs ready

            // fused gate epilogue: 32 rows x 32 cols
            for (int idx = tid; idx < 1024; idx += 384) {
                const int row = idx >> 5, cl = idx & 31;
                const int grow = row0 + c * 32 + row;
                const int gcol = bx * 32 + cl;
                const float aR = Cst[cl * 33 + row];
                const float aZ = Cst[(32 + cl) * 33 + row];
                const float aN = Cst[(64 + cl) * 33 + row];
                float xr, xz, xn;
                if (LAYER == 0) {
                    xr = b1[cl]; xz = b1[32 + cl]; xn = b1[64 + cl];
                    #pragma unroll
                    for (int f = 0; f < DF; f++) {
                        const float xv = xs[row * DF + f];
                        xr += xv * wih[cl * DF + f];
                        xz += xv * wih[(32 + cl) * DF + f];
                        xn += xv * wih[(64 + cl) * DF + f];
                    }
                } else {
                    const size_t xb = ((size_t)grow * TT + t) * G3 + gcol;
                    xr = xin[xb]; xz = xin[xb + HID]; xn = xin[xb + 2 * HID];
                }
                const float r  = sigmoidf_(xr + aR);
                const float z  = sigmoidf_(xz + aZ);
                const float nn = tanhf(xn + r * (aN + bn2[cl]));
                const float hold = As[(c & 1) * (32 * APAD) + row * APAD + gcol];
                const float hv = (1.f - z) * nn + z * hold;
                hw[(size_t)grow * HID + gcol] = hv;
                if (LAYER == 0) hs[((size_t)grow * TT + t) * HID + gcol] = hv;
            }
            __syncthreads();                       // epilogue done: A buf reusable
        }

        if (t < TT - 1) {
            if (tid == 0) {
                __threadfence();
                atomicAdd(&g_bar[rsl], 1);
                volatile int* vb = (volatile int*)&g_bar[rsl];
                const int target = 8 * (t + 1);
                while (*vb < target) __nanosleep(64);
            }
            __syncthreads();
            cp_A(hw, As, row0, 0, tid);            // prefetch chunk0 of next step
        }
    }
}

// ---------------- small kernels ----------------
__global__ void bias_combine(const float* __restrict__ bih, const float* __restrict__ bhh,
                             float* __restrict__ out)
{
    const int i = blockIdx.x * 256 + threadIdx.x;
    if (i < G3) out[i] = bih[i] + ((i < 512) ? bhh[i] : 0.f);
}

__global__ void mb_day_mean()
{
    const int b = blockIdx.x, h = threadIdx.x;
    float s = 0.f;
    for (int st = 0; st < 512; st++) s += g_mb[(b * 512 + st) * HID + h];
    g_mbday[b * HID + h] = s * (1.f / 512.f);
}

__global__ void day_topk(const float* __restrict__ thd)
{
    const int b = blockIdx.x;
    const int d = threadIdx.x;
    __shared__ float sim[NDAYS];
    const float* mbd = g_mbday + b * HID;
    float xn = 0.f;
    for (int i = 0; i < HID; i++) { float v = mbd[i]; xn += v * v; }
    xn = sqrtf(xn);
    if (d < NDAYS) {
        const float* yr = thd + d * HID;
        float yn = 0.f, dot = 0.f;
        for (int i = 0; i < HID; i++) { float y = yr[i]; yn += y * y; dot += mbd[i] * y; }
        const float den = xn * sqrtf(yn);
        sim[d] = (den != 0.f) ? dot / den : 0.f;
    }
    __syncthreads();
    if (d == 0) {
        for (int kk = 0; kk < KDAY; kk++) {
            float best = -1e30f; int bi = 0;
            for (int q = 0; q < NDAYS; q++)
                if (sim[q] > best) { best = sim[q]; bi = q; }
            g_dayidx[b * KDAY + kk] = bi;
            sim[bi] = -1e30f;
        }
    }
}

__global__ void make_rowmap()
{
    const int m = blockIdx.x * 256 + threadIdx.x;
    if (m < NSAMP) g_rowmap[m] = g_dayidx[m >> 9] * 512 + (m & 511);
}

__global__ void rownorm256(const float* __restrict__ X, float* __restrict__ out, int R)
{
    const int warp = (blockIdx.x * blockDim.x + threadIdx.x) >> 5;
    const int lane = threadIdx.x & 31;
    if (warp >= R) return;
    const float* r = X + (size_t)warp * HID;
    float s = 0.f;
    for (int i = lane; i < HID; i += 32) { float v = r[i]; s += v * v; }
    #pragma unroll
    for (int o = 16; o > 0; o >>= 1) s += __shfl_xor_sync(0xffffffffu, s, o);
    if (lane == 0) out[warp] = sqrtf(s);
}

__global__ void neigh_topk()
{
    const int n = blockIdx.x;
    const int tid = threadIdx.x;
    const float* row = g_cs + (size_t)n * NSAMP;

    float tv[NNB]; int ti[NNB];
    #pragma unroll
    for (int i = 0; i < NNB; i++) { tv[i] = -1e30f; ti[i] = 0x7fffffff; }

    for (int it = 0; it < NSAMP / 256; it++) {
        const int idx = tid + it * 256;
        const float v = row[idx];
        if (v > tv[NNB - 1]) {
            int p = NNB - 1;
            while (p > 0 && tv[p - 1] < v) { tv[p] = tv[p - 1]; ti[p] = ti[p - 1]; p--; }
            tv[p] = v; ti[p] = idx;
        }
    }

    __shared__ float sval[256 * NNB];
    __shared__ int   sidx[256 * NNB];
    __shared__ float rv[256];
    __shared__ int   rp[256];
    #pragma unroll
    for (int i = 0; i < NNB; i++) { sval[tid * NNB + i] = tv[i]; sidx[tid * NNB + i] = ti[i]; }
    __syncthreads();

    for (int kk = 0; kk < NNB; kk++) {
        float best = -1e30f; int bp = tid * NNB;
        #pragma unroll
        for (int i = 0; i < NNB; i++) {
            const float v = sval[tid * NNB + i];
            if (v > best) { best = v; bp = tid * NNB + i; }
        }
        rv[tid] = best; rp[tid] = bp;
        __syncthreads();
        for (int s = 128; s > 0; s >>= 1) {
            if (tid < s && rv[tid + s] > rv[tid]) { rv[tid] = rv[tid + s]; rp[tid] = rp[tid + s]; }
            __syncthreads();
        }
        if (tid == 0) {
            const int p = rp[0];
            g_vals[n * NNB + kk] = rv[0];
            g_nidx[n * NNB + kk] = sidx[p];
            sval[p] = -1e30f;
        }
        __syncthreads();
    }
}

__global__ void agg_fc(const float* __restrict__ fc_W, const float* __restrict__ fc_b,
                       float* __restrict__ y)
{
    const int n = blockIdx.x, h = threadIdx.x;
    float agg = 0.f;
    #pragma unroll
    for (int k = 0; k < NNB; k++) {
        const float v = g_vals[n * NNB + k] * (1.f / NNB);
        const int id = g_nidx[n * NNB + k];
        agg += v * g_kh[(size_t)id * HID + h];
    }
    float part = fc_W[h] * g_mb[n * HID + h] + fc_W[HID + h] * agg;
    __shared__ float red[256];
    red[h] = part;
    __syncthreads();
    for (int s = 128; s > 0; s >>= 1) {
        if (h < s) red[h] += red[h + s];
        __syncthreads();
    }
    if (h == 0) y[n] = red[0] + fc_b[0];
}

// ---------------- host ----------------
extern "C" void kernel_launch(void* const* d_in, const int* in_sizes, int n_in,
                              void* d_out, int out_size)
{
    const float* inp       = (const float*)d_in[0];
    const float* train_hid = (const float*)d_in[1];
    const float* thd       = (const float*)d_in[2];
    const float* W_ih0     = (const float*)d_in[3];
    const float* W_hh0     = (const float*)d_in[4];
    const float* b_ih0     = (const float*)d_in[5];
    const float* b_hh0     = (const float*)d_in[6];
    const float* W_ih1     = (const float*)d_in[7];
    const float* W_hh1     = (const float*)d_in[8];
    const float* b_ih1     = (const float*)d_in[9];
    const float* b_hh1     = (const float*)d_in[10];
    const float* lin0_W    = (const float*)d_in[11];
    const float* lin0_b    = (const float*)d_in[12];
    const float* lin1_W    = (const float*)d_in[13];
    const float* lin1_b    = (const float*)d_in[14];
    const float* lin2_W    = (const float*)d_in[15];
    const float* lin2_b    = (const float*)d_in[16];
    const float* proj1_W   = (const float*)d_in[17];
    const float* proj2_W   = (const float*)d_in[18];
    const float* fc_W      = (const float*)d_in[19];
    const float* fc_b      = (const float*)d_in[20];
    (void)in_sizes; (void)n_in; (void)out_size;

    float *p_hp, *p_hs, *p_xw1, *p_bias1, *p_mb1, *p_mb2, *p_mb, *p_kh, *p_khn, *p_q, *p_qn, *p_cs;
    int *p_rowmap, *p_bar;
    cudaGetSymbolAddress((void**)&p_hp, g_hp);
    cudaGetSymbolAddress((void**)&p_bar, g_bar);
    cudaGetSymbolAddress((void**)&p_hs, g_hs);
    cudaGetSymbolAddress((void**)&p_xw1, g_xw1);
    cudaGetSymbolAddress((void**)&p_bias1, g_bias1);
    cudaGetSymbolAddress((void**)&p_mb1, g_mb1);
    cudaGetSymbolAddress((void**)&p_mb2, g_mb2);
    cudaGetSymbolAddress((void**)&p_mb, g_mb);
    cudaGetSymbolAddress((void**)&p_kh, g_kh);
    cudaGetSymbolAddress((void**)&p_khn, g_khn);
    cudaGetSymbolAddress((void**)&p_q, g_q);
    cudaGetSymbolAddress((void**)&p_qn, g_qn);
    cudaGetSymbolAddress((void**)&p_cs, g_cs);
    cudaGetSymbolAddress((void**)&p_rowmap, g_rowmap);

    const int smemp = SMP_FLT * 4;
    cudaFuncSetAttribute(gru_pv2<0>, cudaFuncAttributeMaxDynamicSharedMemorySize, smemp);
    cudaFuncSetAttribute(gru_pv2<1>, cudaFuncAttributeMaxDynamicSharedMemorySize, smemp);

    // ---- GRU layer 0: persistent v2 ----
    cudaMemsetAsync(p_bar, 0, 16 * sizeof(int));
    cudaMemsetAsync(p_hp, 0, BSZ * HID * sizeof(float));       // parity-0 h = 0
    gru_pv2<0><<<128, 384, smemp>>>(W_hh0, b_ih0, b_hh0, inp, W_ih0, p_hp, p_hs);

    // ---- layer-1 input gates: one big 3xTF32 GEMM (combined bias) ----
    bias_combine<<<3, 256>>>(b_ih1, b_hh1, p_bias1);
    gemm_x<<<dim3(G3 / XBN, (BSZ * TT) / XBM), 256>>>(p_hs, W_ih1, p_bias1, p_xw1,
                                                      BSZ * TT, G3, HID, 0, nullptr, nullptr, nullptr);

    // ---- GRU layer 1: persistent v2 ----
    cudaMemsetAsync(p_bar, 0, 16 * sizeof(int));
    cudaMemsetAsync(p_hp, 0, BSZ * HID * sizeof(float));
    gru_pv2<1><<<128, 384, smemp>>>(W_hh1, b_ih1, b_hh1, p_xw1, nullptr, p_hp, nullptr);
    // final h (after t=59) lands in parity-0 buffer = p_hp

    // ---- MLP (leaky relu) ----
    gemm_x<<<dim3(512 / XBN, BSZ / XBM), 256>>>(p_hp, lin0_W, lin0_b, p_mb1,
                                                BSZ, 512, HID, 1, nullptr, nullptr, nullptr);
    gemm_x<<<dim3(512 / XBN, BSZ / XBM), 256>>>(p_mb1, lin1_W, lin1_b, p_mb2,
                                                BSZ, 512, 512, 1, nullptr, nullptr, nullptr);
    gemm_x<<<dim3(HID / XBN, BSZ / XBM), 256>>>(p_mb2, lin2_W, lin2_b, p_mb,
                                                BSZ, HID, 512, 1, nullptr, nullptr, nullptr);

    // ---- day similarity + gather ----
    mb_day_mean<<<4, HID>>>();
    day_topk<<<4, 256>>>(thd);
    make_rowmap<<<NSAMP / 256, 256>>>();
    gemm_x<<<dim3(HID / XBN, NSAMP / XBM), 256>>>(train_hid, proj2_W, nullptr, p_kh,
                                                  NSAMP, HID, HID, 0, p_rowmap, nullptr, nullptr);
    rownorm256<<<(NSAMP * 32) / 256, 256>>>(p_kh, p_khn, NSAMP);

    // ---- queries + cosine sim + neighbor aggregation ----
    gemm_x<<<dim3(HID / XBN, BSZ / XBM), 256>>>(p_mb, proj1_W, nullptr, p_q,
                                                BSZ, HID, HID, 0, nullptr, nullptr, nullptr);
    rownorm256<<<(BSZ * 32) / 256, 256>>>(p_q, p_qn, BSZ);
    gemm_x<<<dim3(NSAMP / XBN, BSZ / XBM), 256>>>(p_q, p_kh, nullptr, p_cs,
                                                  BSZ, NSAMP, HID, 2, nullptr, p_qn, p_khn);
    neigh_topk<<<BSZ, 256>>>();
    agg_fc<<<BSZ, 256>>>(fc_W, fc_b, (float*)d_out);
}

// round 10
// speedup vs baseline: 1.2340x; 1.1250x over previous
#include <cuda_runtime.h>
#include <cmath>
#include <cstdint>

#define BSZ   2048          // B_DAYS * STOCKS
#define TT    60
#define HID   256
#define G3    768           // 3*HID
#define DF    6
#define NSAMP 20480         // 4 * K_DAY * STOCKS
#define NDAYS 240
#define KDAY  10
#define NNB   10

// ---------------- device scratch (no allocations allowed) ----------------
__device__ float g_h[2 * BSZ * HID];          // ping-pong raw h
__device__ float g_hhi[2 * BSZ * HID];        // ping-pong tf32-hi of h
__device__ float g_hlo[2 * BSZ * HID];        // ping-pong tf32-lo of h
__device__ float g_w0hi[G3 * HID];
__device__ float g_w0lo[G3 * HID];
__device__ float g_w1hi[G3 * HID];
__device__ float g_w1lo[G3 * HID];
__device__ float g_hs[BSZ * TT * HID];        // layer-0 hidden sequence
__device__ float g_xw1[(size_t)BSZ * TT * G3];// layer-1 input gates
__device__ float g_bias1[G3];
__device__ float g_mb1[BSZ * 512];
__device__ float g_mb2[BSZ * 512];
__device__ float g_mb[BSZ * HID];
__device__ float g_mbday[4 * HID];
__device__ int   g_dayidx[4 * KDAY];
__device__ int   g_rowmap[NSAMP];
__device__ float g_kh[NSAMP * HID];
__device__ float g_khn[NSAMP];
__device__ float g_q[BSZ * HID];
__device__ float g_qn[BSZ];
__device__ float g_cs[(size_t)BSZ * NSAMP];
__device__ float g_vals[BSZ * NNB];
__device__ int   g_nidx[BSZ * NNB];

// ---------------- tf32 helpers ----------------
__device__ __forceinline__ void split_tf32(float x, uint32_t& hi, uint32_t& lo)
{
    uint32_t h;
    asm("cvt.rna.tf32.f32 %0, %1;" : "=r"(h) : "f"(x));
    float rem = x - __uint_as_float(h);
    uint32_t l;
    asm("cvt.rna.tf32.f32 %0, %1;" : "=r"(l) : "f"(rem));
    hi = h; lo = l;
}

__device__ __forceinline__ void mma_tf32(float* d, const uint32_t* a, const uint32_t* b)
{
    asm volatile(
        "mma.sync.aligned.m16n8k8.row.col.f32.tf32.tf32.f32 "
        "{%0,%1,%2,%3}, {%4,%5,%6,%7}, {%8,%9}, {%0,%1,%2,%3};"
        : "+f"(d[0]), "+f"(d[1]), "+f"(d[2]), "+f"(d[3])
        : "r"(a[0]), "r"(a[1]), "r"(a[2]), "r"(a[3]), "r"(b[0]), "r"(b[1]));
}

__device__ __forceinline__ float sigmoidf_(float x) { return 1.f / (1.f + expf(-x)); }

#define CP_ASYNC16(dst, src) \
    asm volatile("cp.async.cg.shared.global [%0], [%1], 16;\n" :: "r"(dst), "l"(src))
#define CP_COMMIT()  asm volatile("cp.async.commit_group;\n")
#define CP_WAIT1()   asm volatile("cp.async.wait_group 1;\n")
#define CP_WAIT0()   asm volatile("cp.async.wait_group 0;\n")

// ---------------- 3xTF32 tensor-core GEMM: C[M,N] = A[M,K] @ B[N,K]^T + bias ----
// act: 0 none, 1 leaky(0.01), 2 cosine-normalize by rnorm[m]*cnorm[n]
#define XBM 128
#define XBN 64
#define XBK 32
#define XPAD 36

__global__ void gemm_x(const float* __restrict__ A, const float* __restrict__ B,
                       const float* __restrict__ bias, float* __restrict__ C,
                       int M, int N, int K, int act,
                       const int* __restrict__ rowmap,
                       const float* __restrict__ rnorm, const float* __restrict__ cnorm)
{
    __shared__ float As[XBM][XPAD];   // [m][k]
    __shared__ float Bs[XBN][XPAD];   // [n][k]
    const int bm = blockIdx.y * XBM;
    const int bn = blockIdx.x * XBN;
    const int tid = threadIdx.x;                 // 256
    const int warp = tid >> 5, lane = tid & 31;
    const int wm = (warp & 3) * 32;
    const int wn = (warp >> 2) * 32;
    const int g = lane >> 2, tg = lane & 3;

    float acc[2][4][4];
    #pragma unroll
    for (int a = 0; a < 2; a++)
        #pragma unroll
        for (int b = 0; b < 4; b++)
            #pragma unroll
            for (int c = 0; c < 4; c++) acc[a][b][c] = 0.f;

    for (int k0 = 0; k0 < K; k0 += XBK) {
        #pragma unroll
        for (int i = 0; i < 4; i++) {
            int idx = tid + i * 256;                   // 0..1023
            int r = idx >> 3, c4 = (idx & 7) * 4;
            int arow = bm + r;
            if (rowmap) arow = rowmap[arow];
            float4 v = *(const float4*)(A + (size_t)arow * K + k0 + c4);
            As[r][c4 + 0] = v.x; As[r][c4 + 1] = v.y;
            As[r][c4 + 2] = v.z; As[r][c4 + 3] = v.w;
        }
        #pragma unroll
        for (int i = 0; i < 2; i++) {
            int idx = tid + i * 256;                   // 0..511
            int r = idx >> 3, c4 = (idx & 7) * 4;
            float4 v = *(const float4*)(B + (size_t)(bn + r) * K + k0 + c4);
            Bs[r][c4 + 0] = v.x; Bs[r][c4 + 1] = v.y;
            Bs[r][c4 + 2] = v.z; Bs[r][c4 + 3] = v.w;
        }
        __syncthreads();
        #pragma unroll
        for (int kc = 0; kc < 4; kc++) {
            const int kb = kc * 8;
            uint32_t ahi[2][4], alo[2][4];
            #pragma unroll
            for (int mt = 0; mt < 2; mt++) {
                const int r0 = wm + mt * 16;
                split_tf32(As[r0 + g][kb + tg],         ahi[mt][0], alo[mt][0]);
                split_tf32(As[r0 + g + 8][kb + tg],     ahi[mt][1], alo[mt][1]);
                split_tf32(As[r0 + g][kb + tg + 4],     ahi[mt][2], alo[mt][2]);
                split_tf32(As[r0 + g + 8][kb + tg + 4], ahi[mt][3], alo[mt][3]);
            }
            uint32_t bhi[4][2], blo[4][2];
            #pragma unroll
            for (int nt = 0; nt < 4; nt++) {
                const int c0 = wn + nt * 8;
                split_tf32(Bs[c0 + g][kb + tg],     bhi[nt][0], blo[nt][0]);
                split_tf32(Bs[c0 + g][kb + tg + 4], bhi[nt][1], blo[nt][1]);
            }
            #pragma unroll
            for (int mt = 0; mt < 2; mt++)
                #pragma unroll
                for (int nt = 0; nt < 4; nt++) {
                    mma_tf32(acc[mt][nt], alo[mt], bhi[nt]);
                    mma_tf32(acc[mt][nt], ahi[mt], blo[nt]);
                    mma_tf32(acc[mt][nt], ahi[mt], bhi[nt]);
                }
        }
        __syncthreads();
    }

    #pragma unroll
    for (int mt = 0; mt < 2; mt++) {
        #pragma unroll
        for (int nt = 0; nt < 4; nt++) {
            const int r0 = bm + wm + mt * 16 + g;
            const int c0 = bn + wn + nt * 8 + tg * 2;
            #pragma unroll
            for (int ci = 0; ci < 4; ci++) {
                const int m = r0 + ((ci >> 1) ? 8 : 0);
                const int nn = c0 + (ci & 1);
                float v = acc[mt][nt][ci];
                if (bias) v += bias[nn];
                if (act == 1) {
                    v = (v >= 0.f) ? v : 0.01f * v;
                } else if (act == 2) {
                    float den = rnorm[m] * cnorm[nn];
                    v = (den != 0.f) ? v / den : 0.f;
                }
                C[(size_t)m * N + nn] = v;
            }
        }
    }
}

// ---------------- pre-split GRU step kernels (per-step launch, v3) ----------------
// CTA: 64 rows x 32 gate-cols (x3 gates). grid (8, 32), 128 thr.
// Whh pre-split in global (hi/lo); h pre-split by previous epilogue (hi/lo).
// Mainloop: cp.async double-buffered chunks, pure LDS+mma (no cvt).
// LAYER==1 bias contract: xin (g_xw1) ALREADY contains b_ih1+b_hh1 for r,z and
// b_ih1 for n; the epilogue must add ONLY bhh_n (inside tanh). LAYER==0: xr/xz/xn
// carry only b_ih0, so all three bhh components are added here.
#define GM 64
#define GN 32
#define GK 32
#define GP 36
#define SM_A (GM * GP)      // 2304 floats per buffer per array
#define SM_B (96 * GP)      // 3456

#define OFF_AL (2 * SM_A)
#define OFF_BH (4 * SM_A)
#define OFF_BL (4 * SM_A + 2 * SM_B)
#define OFF_EX (4 * SM_A + 4 * SM_B)
#define SMG_FLT (OFF_EX + 96 + 96 + 32 * 3 * DF + GM * DF)

__device__ __forceinline__ void gru_load_chunk(
    float* sm, const float* __restrict__ hhi, const float* __restrict__ hlo,
    const float* __restrict__ whi, const float* __restrict__ wlo,
    int bm, int bn, int k0, int buf, int tid)
{
    // A tiles: 64 rows x 32 k = 512 float4 per array -> 4 iters
    #pragma unroll
    for (int i = 0; i < 4; i++) {
        int idx = tid + i * 128;
        int rr = idx >> 3, cc = (idx & 7) * 4;
        const size_t gsrc = (size_t)(bm + rr) * HID + k0 + cc;
        uint32_t d1 = (uint32_t)__cvta_generic_to_shared(sm + buf * SM_A + rr * GP + cc);
        CP_ASYNC16(d1, hhi + gsrc);
        uint32_t d2 = (uint32_t)__cvta_generic_to_shared(sm + OFF_AL + buf * SM_A + rr * GP + cc);
        CP_ASYNC16(d2, hlo + gsrc);
    }
    // B tiles: 96 gates x 32 k = 768 float4 per array -> 6 iters
    #pragma unroll
    for (int i = 0; i < 6; i++) {
        int idx = tid + i * 128;
        int nl = idx >> 3, cc = (idx & 7) * 4;
        const int grow = (nl >> 5) * HID + bn + (nl & 31);
        const size_t gsrc = (size_t)grow * HID + k0 + cc;
        uint32_t d1 = (uint32_t)__cvta_generic_to_shared(sm + OFF_BH + buf * SM_B + nl * GP + cc);
        CP_ASYNC16(d1, whi + gsrc);
        uint32_t d2 = (uint32_t)__cvta_generic_to_shared(sm + OFF_BL + buf * SM_B + nl * GP + cc);
        CP_ASYNC16(d2, wlo + gsrc);
    }
    CP_COMMIT();
}

template<int LAYER>
__global__ void __launch_bounds__(128) gru_v3(
    const float* __restrict__ hin, const float* __restrict__ hin_hi,
    const float* __restrict__ hin_lo, float* __restrict__ hout,
    float* __restrict__ hout_hi, float* __restrict__ hout_lo,
    const float* __restrict__ whi, const float* __restrict__ wlo,
    const float* __restrict__ bhh, const float* __restrict__ xin,
    const float* __restrict__ Wih, const float* __restrict__ bih, int t)
{
    extern __shared__ float sm[];
    float* bih_s = sm + OFF_EX;         // [96] (layer0)
    float* bhh_s = bih_s + 96;          // [96]
    float* wih_s = bhh_s + 96;          // [32][3*DF] (layer0)
    float* xs    = wih_s + 32 * 3 * DF; // [64][DF] (layer0)

    const int tid = threadIdx.x;
    const int warp = tid >> 5, lane = tid & 31;
    const int wm = (warp & 1) * 32;          // 2 m-warps of 32 rows
    const int wn = (warp >> 1) * 16;         // 2 n-warps of 16 cols
    const int g = lane >> 2, tg = lane & 3;
    const int bn = blockIdx.x * GN;
    const int bm = blockIdx.y * GM;

    if (tid < 96) {
        const int gg = tid >> 5, c = tid & 31;
        bhh_s[tid] = bhh[gg * HID + bn + c];
        if (LAYER == 0) bih_s[tid] = bih[gg * HID + bn + c];
    }
    if (LAYER == 0) {
        for (int i = tid; i < 32 * 3 * DF; i += 128) {
            const int c = i / (3 * DF), r = i % (3 * DF);
            wih_s[i] = Wih[((r / DF) * HID + bn + c) * DF + (r % DF)];
        }
        for (int i = tid; i < GM * DF; i += 128) {
            const int r = i / DF, f = i % DF;
            xs[i] = xin[(bm + r) * (DF * TT) + f * TT + t];
        }
    }

    gru_load_chunk(sm, hin_hi, hin_lo, whi, wlo, bm, bn, 0, 0, tid);

    float acc[3][2][2][4];
    #pragma unroll
    for (int a = 0; a < 3; a++)
        #pragma unroll
        for (int b = 0; b < 2; b++)
            #pragma unroll
            for (int c = 0; c < 2; c++)
                #pragma unroll
                for (int d = 0; d < 4; d++) acc[a][b][c][d] = 0.f;

    #pragma unroll
    for (int ch = 0; ch < 8; ch++) {
        if (ch < 7) { gru_load_chunk(sm, hin_hi, hin_lo, whi, wlo, bm, bn, (ch + 1) * GK, (ch + 1) & 1, tid); CP_WAIT1(); }
        else        { CP_WAIT0(); }
        __syncthreads();

        const float* Ah = sm + (ch & 1) * SM_A;
        const float* Al = sm + OFF_AL + (ch & 1) * SM_A;
        const float* Bh = sm + OFF_BH + (ch & 1) * SM_B;
        const float* Bl = sm + OFF_BL + (ch & 1) * SM_B;

        #pragma unroll
        for (int ks = 0; ks < 4; ks++) {
            const int kb = ks * 8;
            uint32_t ah[2][4], al[2][4];
            #pragma unroll
            for (int mt = 0; mt < 2; mt++) {
                const int rb = wm + mt * 16;
                ah[mt][0] = __float_as_uint(Ah[(rb + g) * GP + kb + tg]);
                ah[mt][1] = __float_as_uint(Ah[(rb + g + 8) * GP + kb + tg]);
                ah[mt][2] = __float_as_uint(Ah[(rb + g) * GP + kb + tg + 4]);
                ah[mt][3] = __float_as_uint(Ah[(rb + g + 8) * GP + kb + tg + 4]);
                al[mt][0] = __float_as_uint(Al[(rb + g) * GP + kb + tg]);
                al[mt][1] = __float_as_uint(Al[(rb + g + 8) * GP + kb + tg]);
                al[mt][2] = __float_as_uint(Al[(rb + g) * GP + kb + tg + 4]);
                al[mt][3] = __float_as_uint(Al[(rb + g + 8) * GP + kb + tg + 4]);
            }
            #pragma unroll
            for (int gg = 0; gg < 3; gg++) {
                #pragma unroll
                for (int nt = 0; nt < 2; nt++) {
                    const int n = gg * GN + wn + nt * 8 + g;
                    uint32_t bh[2], bl[2];
                    bh[0] = __float_as_uint(Bh[n * GP + kb + tg]);
                    bh[1] = __float_as_uint(Bh[n * GP + kb + tg + 4]);
                    bl[0] = __float_as_uint(Bl[n * GP + kb + tg]);
                    bl[1] = __float_as_uint(Bl[n * GP + kb + tg + 4]);
                    #pragma unroll
                    for (int mt = 0; mt < 2; mt++) {
                        mma_tf32(acc[gg][mt][nt], al[mt], bh);
                        mma_tf32(acc[gg][mt][nt], ah[mt], bl);
                        mma_tf32(acc[gg][mt][nt], ah[mt], bh);
                    }
                }
            }
        }
        __syncthreads();
    }

    #pragma unroll
    for (int mt = 0; mt < 2; mt++) {
        #pragma unroll
        for (int nt = 0; nt < 2; nt++) {
            #pragma unroll
            for (int ci = 0; ci < 4; ci++) {
                const int rl = wm + mt * 16 + g + ((ci >> 1) ? 8 : 0);
                const int cl = wn + nt * 8 + tg * 2 + (ci & 1);
                const int row = bm + rl, col = bn + cl;
                float r, z, nn;
                if (LAYER == 0) {
                    float xr = bih_s[cl], xz = bih_s[32 + cl], xn = bih_s[64 + cl];
                    #pragma unroll
                    for (int f = 0; f < DF; f++) {
                        const float xv = xs[rl * DF + f];
                        xr += xv * wih_s[cl * 3 * DF + f];
                        xz += xv * wih_s[cl * 3 * DF + DF + f];
                        xn += xv * wih_s[cl * 3 * DF + 2 * DF + f];
                    }
                    r  = sigmoidf_(xr + acc[0][mt][nt][ci] + bhh_s[cl]);
                    z  = sigmoidf_(xz + acc[1][mt][nt][ci] + bhh_s[32 + cl]);
                    nn = tanhf(xn + r * (acc[2][mt][nt][ci] + bhh_s[64 + cl]));
                } else {
                    // xin already holds bih+bhh for r,z and bih for n (bias_combine)
                    const size_t xb = ((size_t)row * TT + t) * G3 + col;
                    const float xr = xin[xb];
                    const float xz = xin[xb + HID];
                    const float xn = xin[xb + 2 * HID];
                    r  = sigmoidf_(xr + acc[0][mt][nt][ci]);
                    z  = sigmoidf_(xz + acc[1][mt][nt][ci]);
                    nn = tanhf(xn + r * (acc[2][mt][nt][ci] + bhh_s[64 + cl]));
                }
                const float ho = hin[(size_t)row * HID + col];
                const float hv = (1.f - z) * nn + z * ho;
                const size_t oidx = (size_t)row * HID + col;
                hout[oidx] = hv;
                uint32_t hi, lo; split_tf32(hv, hi, lo);
                hout_hi[oidx] = __uint_as_float(hi);
                hout_lo[oidx] = __uint_as_float(lo);
                if (LAYER == 0) g_hs[((size_t)row * TT + t) * HID + col] = hv;
            }
        }
    }
}

// ---------------- small kernels ----------------
__global__ void split_mat(const float* __restrict__ in, float* __restrict__ ohi,
                          float* __restrict__ olo, int n)
{
    const int i = blockIdx.x * 256 + threadIdx.x;
    if (i < n) {
        uint32_t h, l;
        split_tf32(in[i], h, l);
        ohi[i] = __uint_as_float(h);
        olo[i] = __uint_as_float(l);
    }
}

__global__ void bias_combine(const float* __restrict__ bih, const float* __restrict__ bhh,
                             float* __restrict__ out)
{
    const int i = blockIdx.x * 256 + threadIdx.x;
    if (i < G3) out[i] = bih[i] + ((i < 512) ? bhh[i] : 0.f);
}

__global__ void mb_day_mean()
{
    const int b = blockIdx.x, h = threadIdx.x;
    float s = 0.f;
    for (int st = 0; st < 512; st++) s += g_mb[(b * 512 + st) * HID + h];
    g_mbday[b * HID + h] = s * (1.f / 512.f);
}

__global__ void day_topk(const float* __restrict__ thd)
{
    const int b = blockIdx.x;
    const int d = threadIdx.x;
    __shared__ float sim[NDAYS];
    const float* mbd = g_mbday + b * HID;
    float xn = 0.f;
    for (int i = 0; i < HID; i++) { float v = mbd[i]; xn += v * v; }
    xn = sqrtf(xn);
    if (d < NDAYS) {
        const float* yr = thd + d * HID;
        float yn = 0.f, dot = 0.f;
        for (int i = 0; i < HID; i++) { float y = yr[i]; yn += y * y; dot += mbd[i] * y; }
        const float den = xn * sqrtf(yn);
        sim[d] = (den != 0.f) ? dot / den : 0.f;
    }
    __syncthreads();
    if (d == 0) {
        for (int kk = 0; kk < KDAY; kk++) {
            float best = -1e30f; int bi = 0;
            for (int q = 0; q < NDAYS; q++)
                if (sim[q] > best) { best = sim[q]; bi = q; }
            g_dayidx[b * KDAY + kk] = bi;
            sim[bi] = -1e30f;
        }
    }
}

__global__ void make_rowmap()
{
    const int m = blockIdx.x * 256 + threadIdx.x;
    if (m < NSAMP) g_rowmap[m] = g_dayidx[m >> 9] * 512 + (m & 511);
}

__global__ void rownorm256(const float* __restrict__ X, float* __restrict__ out, int R)
{
    const int warp = (blockIdx.x * blockDim.x + threadIdx.x) >> 5;
    const int lane = threadIdx.x & 31;
    if (warp >= R) return;
    const float* r = X + (size_t)warp * HID;
    float s = 0.f;
    for (int i = lane; i < HID; i += 32) { float v = r[i]; s += v * v; }
    #pragma unroll
    for (int o = 16; o > 0; o >>= 1) s += __shfl_xor_sync(0xffffffffu, s, o);
    if (lane == 0) out[warp] = sqrtf(s);
}

__global__ void neigh_topk()
{
    const int n = blockIdx.x;
    const int tid = threadIdx.x;
    const float* row = g_cs + (size_t)n * NSAMP;

    float tv[NNB]; int ti[NNB];
    #pragma unroll
    for (int i = 0; i < NNB; i++) { tv[i] = -1e30f; ti[i] = 0x7fffffff; }

    for (int it = 0; it < NSAMP / 256; it++) {
        const int idx = tid + it * 256;
        const float v = row[idx];
        if (v > tv[NNB - 1]) {
            int p = NNB - 1;
            while (p > 0 && tv[p - 1] < v) { tv[p] = tv[p - 1]; ti[p] = ti[p - 1]; p--; }
            tv[p] = v; ti[p] = idx;
        }
    }

    __shared__ float sval[256 * NNB];
    __shared__ int   sidx[256 * NNB];
    __shared__ float rv[256];
    __shared__ int   rp[256];
    #pragma unroll
    for (int i = 0; i < NNB; i++) { sval[tid * NNB + i] = tv[i]; sidx[tid * NNB + i] = ti[i]; }
    __syncthreads();

    for (int kk = 0; kk < NNB; kk++) {
        float best = -1e30f; int bp = tid * NNB;
        #pragma unroll
        for (int i = 0; i < NNB; i++) {
            const float v = sval[tid * NNB + i];
            if (v > best) { best = v; bp = tid * NNB + i; }
        }
        rv[tid] = best; rp[tid] = bp;
        __syncthreads();
        for (int s = 128; s > 0; s >>= 1) {
            if (tid < s && rv[tid + s] > rv[tid]) { rv[tid] = rv[tid + s]; rp[tid] = rp[tid + s]; }
            __syncthreads();
        }
        if (tid == 0) {
            const int p = rp[0];
            g_vals[n * NNB + kk] = rv[0];
            g_nidx[n * NNB + kk] = sidx[p];
            sval[p] = -1e30f;
        }
        __syncthreads();
    }
}

__global__ void agg_fc(const float* __restrict__ fc_W, const float* __restrict__ fc_b,
                       float* __restrict__ y)
{
    const int n = blockIdx.x, h = threadIdx.x;
    float agg = 0.f;
    #pragma unroll
    for (int k = 0; k < NNB; k++) {
        const float v = g_vals[n * NNB + k] * (1.f / NNB);
        const int id = g_nidx[n * NNB + k];
        agg += v * g_kh[(size_t)id * HID + h];
    }
    float part = fc_W[h] * g_mb[n * HID + h] + fc_W[HID + h] * agg;
    __shared__ float red[256];
    red[h] = part;
    __syncthreads();
    for (int s = 128; s > 0; s >>= 1) {
        if (h < s) red[h] += red[h + s];
        __syncthreads();
    }
    if (h == 0) y[n] = red[0] + fc_b[0];
}

// ---------------- host ----------------
extern "C" void kernel_launch(void* const* d_in, const int* in_sizes, int n_in,
                              void* d_out, int out_size)
{
    const float* inp       = (const float*)d_in[0];
    const float* train_hid = (const float*)d_in[1];
    const float* thd       = (const float*)d_in[2];
    const float* W_ih0     = (const float*)d_in[3];
    const float* W_hh0     = (const float*)d_in[4];
    const float* b_ih0     = (const float*)d_in[5];
    const float* b_hh0     = (const float*)d_in[6];
    const float* W_ih1     = (const float*)d_in[7];
    const float* W_hh1     = (const float*)d_in[8];
    const float* b_ih1     = (const float*)d_in[9];
    const float* b_hh1     = (const float*)d_in[10];
    const float* lin0_W    = (const float*)d_in[11];
    const float* lin0_b    = (const float*)d_in[12];
    const float* lin1_W    = (const float*)d_in[13];
    const float* lin1_b    = (const float*)d_in[14];
    const float* lin2_W    = (const float*)d_in[15];
    const float* lin2_b    = (const float*)d_in[16];
    const float* proj1_W   = (const float*)d_in[17];
    const float* proj2_W   = (const float*)d_in[18];
    const float* fc_W      = (const float*)d_in[19];
    const float* fc_b      = (const float*)d_in[20];
    (void)in_sizes; (void)n_in; (void)out_size;

    float *p_h, *p_hhi, *p_hlo, *p_w0hi, *p_w0lo, *p_w1hi, *p_w1lo;
    float *p_hs, *p_xw1, *p_bias1, *p_mb1, *p_mb2, *p_mb, *p_kh, *p_khn, *p_q, *p_qn, *p_cs;
    int *p_rowmap;
    cudaGetSymbolAddress((void**)&p_h, g_h);
    cudaGetSymbolAddress((void**)&p_hhi, g_hhi);
    cudaGetSymbolAddress((void**)&p_hlo, g_hlo);
    cudaGetSymbolAddress((void**)&p_w0hi, g_w0hi);
    cudaGetSymbolAddress((void**)&p_w0lo, g_w0lo);
    cudaGetSymbolAddress((void**)&p_w1hi, g_w1hi);
    cudaGetSymbolAddress((void**)&p_w1lo, g_w1lo);
    cudaGetSymbolAddress((void**)&p_hs, g_hs);
    cudaGetSymbolAddress((void**)&p_xw1, g_xw1);
    cudaGetSymbolAddress((void**)&p_bias1, g_bias1);
    cudaGetSymbolAddress((void**)&p_mb1, g_mb1);
    cudaGetSymbolAddress((void**)&p_mb2, g_mb2);
    cudaGetSymbolAddress((void**)&p_mb, g_mb);
    cudaGetSymbolAddress((void**)&p_kh, g_kh);
    cudaGetSymbolAddress((void**)&p_khn, g_khn);
    cudaGetSymbolAddress((void**)&p_q, g_q);
    cudaGetSymbolAddress((void**)&p_qn, g_qn);
    cudaGetSymbolAddress((void**)&p_cs, g_cs);
    cudaGetSymbolAddress((void**)&p_rowmap, g_rowmap);

    const int smg = SMG_FLT * 4;
    cudaFuncSetAttribute(gru_v3<0>, cudaFuncAttributeMaxDynamicSharedMemorySize, smg);
    cudaFuncSetAttribute(gru_v3<1>, cudaFuncAttributeMaxDynamicSharedMemorySize, smg);

    const size_t HN = (size_t)BSZ * HID;
    const dim3 gru_grid(HID / GN, BSZ / GM);   // (8, 32)

    // ---- pre-split recurrent weights ----
    split_mat<<<(G3 * HID + 255) / 256, 256>>>(W_hh0, p_w0hi, p_w0lo, G3 * HID);
    split_mat<<<(G3 * HID + 255) / 256, 256>>>(W_hh1, p_w1hi, p_w1lo, G3 * HID);

    // ---- GRU layer 0 ----
    cudaMemsetAsync(p_h, 0, HN * sizeof(float));
    cudaMemsetAsync(p_hhi, 0, HN * sizeof(float));
    cudaMemsetAsync(p_hlo, 0, HN * sizeof(float));
    for (int t = 0; t < TT; t++) {
        const int pr = t & 1, pw = pr ^ 1;
        gru_v3<0><<<gru_grid, 128, smg>>>(
            p_h + pr * HN, p_hhi + pr * HN, p_hlo + pr * HN,
            p_h + pw * HN, p_hhi + pw * HN, p_hlo + pw * HN,
            p_w0hi, p_w0lo, b_hh0, inp, W_ih0, b_ih0, t);
    }

    // ---- layer-1 input gates: one big 3xTF32 GEMM (combined bias) ----
    bias_combine<<<3, 256>>>(b_ih1, b_hh1, p_bias1);
    gemm_x<<<dim3(G3 / XBN, (BSZ * TT) / XBM), 256>>>(p_hs, W_ih1, p_bias1, p_xw1,
                                                      BSZ * TT, G3, HID, 0, nullptr, nullptr, nullptr);

    // ---- GRU layer 1 ----
    cudaMemsetAsync(p_h, 0, HN * sizeof(float));
    cudaMemsetAsync(p_hhi, 0, HN * sizeof(float));
    cudaMemsetAsync(p_hlo, 0, HN * sizeof(float));
    for (int t = 0; t < TT; t++) {
        const int pr = t & 1, pw = pr ^ 1;
        gru_v3<1><<<gru_grid, 128, smg>>>(
            p_h + pr * HN, p_hhi + pr * HN, p_hlo + pr * HN,
            p_h + pw * HN, p_hhi + pw * HN, p_hlo + pw * HN,
            p_w1hi, p_w1lo, b_hh1, p_xw1, nullptr, nullptr, t);
    }
    // t=59 writes parity 0 -> final h at p_h

    // ---- MLP (leaky relu) ----
    gemm_x<<<dim3(512 / XBN, BSZ / XBM), 256>>>(p_h, lin0_W, lin0_b, p_mb1,
                                                BSZ, 512, HID, 1, nullptr, nullptr, nullptr);
    gemm_x<<<dim3(512 / XBN, BSZ / XBM), 256>>>(p_mb1, lin1_W, lin1_b, p_mb2,
                                                BSZ, 512, 512, 1, nullptr, nullptr, nullptr);
    gemm_x<<<dim3(HID / XBN, BSZ / XBM), 256>>>(p_mb2, lin2_W, lin2_b, p_mb,
                                                BSZ, HID, 512, 1, nullptr, nullptr, nullptr);

    // ---- day similarity + gather ----
    mb_day_mean<<<4, HID>>>();
    day_topk<<<4, 256>>>(thd);
    make_rowmap<<<NSAMP / 256, 256>>>();
    gemm_x<<<dim3(HID / XBN, NSAMP / XBM), 256>>>(train_hid, proj2_W, nullptr, p_kh,
                                                  NSAMP, HID, HID, 0, p_rowmap, nullptr, nullptr);
    rownorm256<<<(NSAMP * 32) / 256, 256>>>(p_kh, p_khn, NSAMP);

    // ---- queries + cosine sim + neighbor aggregation ----
    gemm_x<<<dim3(HID / XBN, BSZ / XBM), 256>>>(p_mb, proj1_W, nullptr, p_q,
                                                BSZ, HID, HID, 0, nullptr, nullptr, nullptr);
    rownorm256<<<(BSZ * 32) / 256, 256>>>(p_q, p_qn, BSZ);
    gemm_x<<<dim3(NSAMP / XBN, BSZ / XBM), 256>>>(p_q, p_kh, nullptr, p_cs,
                                                  BSZ, NSAMP, HID, 2, nullptr, p_qn, p_khn);
    neigh_topk<<<BSZ, 256>>>();
    agg_fc<<<BSZ, 256>>>(fc_W, fc_b, (float*)d_out);
}

// round 11
// speedup vs baseline: 1.3670x; 1.1078x over previous
#include <cuda_runtime.h>
#include <cmath>
#include <cstdint>

#define BSZ   2048          // B_DAYS * STOCKS
#define TT    60
#define HID   256
#define G3    768           // 3*HID
#define DF    6
#define NSAMP 20480         // 4 * K_DAY * STOCKS
#define NDAYS 240
#define KDAY  10
#define NNB   10

// ---------------- device scratch (no allocations allowed) ----------------
__device__ float g_h[2 * BSZ * HID];          // ping-pong raw h (row-major)
__device__ float g_hhi[2 * BSZ * HID];        // ping-pong tf32-hi of h (FRAG-PACKED)
__device__ float g_hlo[2 * BSZ * HID];        // ping-pong tf32-lo of h (FRAG-PACKED)
__device__ float g_w0hi[G3 * HID];            // Whh0 hi (FRAG-PACKED)
__device__ float g_w0lo[G3 * HID];
__device__ float g_w1hi[G3 * HID];
__device__ float g_w1lo[G3 * HID];
__device__ float g_hs[BSZ * TT * HID];        // layer-0 hidden sequence
__device__ float g_xw1[(size_t)BSZ * TT * G3];// layer-1 input gates
__device__ float g_bias1[G3];
__device__ float g_mb1[BSZ * 512];
__device__ float g_mb2[BSZ * 512];
__device__ float g_mb[BSZ * HID];
__device__ float g_mbday[4 * HID];
__device__ int   g_dayidx[4 * KDAY];
__device__ int   g_rowmap[NSAMP];
__device__ float g_kh[NSAMP * HID];
__device__ float g_khn[NSAMP];
__device__ float g_q[BSZ * HID];
__device__ float g_qn[BSZ];
__device__ float g_cs[(size_t)BSZ * NSAMP];
__device__ float g_vals[BSZ * NNB];
__device__ int   g_nidx[BSZ * NNB];

// ---------------- tf32 helpers ----------------
__device__ __forceinline__ void split_tf32(float x, uint32_t& hi, uint32_t& lo)
{
    uint32_t h;
    asm("cvt.rna.tf32.f32 %0, %1;" : "=r"(h) : "f"(x));
    float rem = x - __uint_as_float(h);
    uint32_t l;
    asm("cvt.rna.tf32.f32 %0, %1;" : "=r"(l) : "f"(rem));
    hi = h; lo = l;
}

__device__ __forceinline__ void mma_tf32(float* d, const uint32_t* a, const uint32_t* b)
{
    asm volatile(
        "mma.sync.aligned.m16n8k8.row.col.f32.tf32.tf32.f32 "
        "{%0,%1,%2,%3}, {%4,%5,%6,%7}, {%8,%9}, {%0,%1,%2,%3};"
        : "+f"(d[0]), "+f"(d[1]), "+f"(d[2]), "+f"(d[3])
        : "r"(a[0]), "r"(a[1]), "r"(a[2]), "r"(a[3]), "r"(b[0]), "r"(b[1]));
}

__device__ __forceinline__ float sigmoidf_(float x) { return 1.f / (1.f + expf(-x)); }

#define CP_ASYNC16(dst, src) \
    asm volatile("cp.async.cg.shared.global [%0], [%1], 16;\n" :: "r"(dst), "l"(src))
#define CP_COMMIT()  asm volatile("cp.async.commit_group;\n")
#define CP_WAIT1()   asm volatile("cp.async.wait_group 1;\n")
#define CP_WAIT0()   asm volatile("cp.async.wait_group 0;\n")

// packed index helpers.
// A-frag pack (h): 16x8 tile -> [lane][word]: lane=(r%8)*4+(c%4), word=((r>>3)&1)+2*((c>>2)&1)
__device__ __forceinline__ size_t hpack_idx(int row, int col)
{
    return ((size_t)(row >> 4) * 32 + (col >> 3)) * 128
         + (((row & 7) << 2) + (col & 3)) * 4
         + ((row >> 3) & 1) + (((col >> 2) & 1) << 1);
}
// B-frag pack (W): 8(gate)x8(k) tile -> [lane][word]: lane=(gate%8)*4+(k%4), word=(k>>2)&1
__device__ __forceinline__ size_t wpack_idx(int gate, int k)
{
    return ((size_t)(gate >> 3) * 32 + (k >> 3)) * 64
         + (((gate & 7) << 2) + (k & 3)) * 2 + ((k >> 2) & 1);
}

// ---------------- 3xTF32 tensor-core GEMM: C[M,N] = A[M,K] @ B[N,K]^T + bias ----
// act: 0 none, 1 leaky(0.01), 2 cosine-normalize by rnorm[m]*cnorm[n]
#define XBM 128
#define XBN 64
#define XBK 32
#define XPAD 36

__global__ void gemm_x(const float* __restrict__ A, const float* __restrict__ B,
                       const float* __restrict__ bias, float* __restrict__ C,
                       int M, int N, int K, int act,
                       const int* __restrict__ rowmap,
                       const float* __restrict__ rnorm, const float* __restrict__ cnorm)
{
    __shared__ float As[XBM][XPAD];   // [m][k]
    __shared__ float Bs[XBN][XPAD];   // [n][k]
    const int bm = blockIdx.y * XBM;
    const int bn = blockIdx.x * XBN;
    const int tid = threadIdx.x;                 // 256
    const int warp = tid >> 5, lane = tid & 31;
    const int wm = (warp & 3) * 32;
    const int wn = (warp >> 2) * 32;
    const int g = lane >> 2, tg = lane & 3;

    float acc[2][4][4];
    #pragma unroll
    for (int a = 0; a < 2; a++)
        #pragma unroll
        for (int b = 0; b < 4; b++)
            #pragma unroll
            for (int c = 0; c < 4; c++) acc[a][b][c] = 0.f;

    for (int k0 = 0; k0 < K; k0 += XBK) {
        #pragma unroll
        for (int i = 0; i < 4; i++) {
            int idx = tid + i * 256;                   // 0..1023
            int r = idx >> 3, c4 = (idx & 7) * 4;
            int arow = bm + r;
            if (rowmap) arow = rowmap[arow];
            float4 v = *(const float4*)(A + (size_t)arow * K + k0 + c4);
            As[r][c4 + 0] = v.x; As[r][c4 + 1] = v.y;
            As[r][c4 + 2] = v.z; As[r][c4 + 3] = v.w;
        }
        #pragma unroll
        for (int i = 0; i < 2; i++) {
            int idx = tid + i * 256;                   // 0..511
            int r = idx >> 3, c4 = (idx & 7) * 4;
            float4 v = *(const float4*)(B + (size_t)(bn + r) * K + k0 + c4);
            Bs[r][c4 + 0] = v.x; Bs[r][c4 + 1] = v.y;
            Bs[r][c4 + 2] = v.z; Bs[r][c4 + 3] = v.w;
        }
        __syncthreads();
        #pragma unroll
        for (int kc = 0; kc < 4; kc++) {
            const int kb = kc * 8;
            uint32_t ahi[2][4], alo[2][4];
            #pragma unroll
            for (int mt = 0; mt < 2; mt++) {
                const int r0 = wm + mt * 16;
                split_tf32(As[r0 + g][kb + tg],         ahi[mt][0], alo[mt][0]);
                split_tf32(As[r0 + g + 8][kb + tg],     ahi[mt][1], alo[mt][1]);
                split_tf32(As[r0 + g][kb + tg + 4],     ahi[mt][2], alo[mt][2]);
                split_tf32(As[r0 + g + 8][kb + tg + 4], ahi[mt][3], alo[mt][3]);
            }
            uint32_t bhi[4][2], blo[4][2];
            #pragma unroll
            for (int nt = 0; nt < 4; nt++) {
                const int c0 = wn + nt * 8;
                split_tf32(Bs[c0 + g][kb + tg],     bhi[nt][0], blo[nt][0]);
                split_tf32(Bs[c0 + g][kb + tg + 4], bhi[nt][1], blo[nt][1]);
            }
            #pragma unroll
            for (int mt = 0; mt < 2; mt++)
                #pragma unroll
                for (int nt = 0; nt < 4; nt++) {
                    mma_tf32(acc[mt][nt], alo[mt], bhi[nt]);
                    mma_tf32(acc[mt][nt], ahi[mt], blo[nt]);
                    mma_tf32(acc[mt][nt], ahi[mt], bhi[nt]);
                }
        }
        __syncthreads();
    }

    #pragma unroll
    for (int mt = 0; mt < 2; mt++) {
        #pragma unroll
        for (int nt = 0; nt < 4; nt++) {
            const int r0 = bm + wm + mt * 16 + g;
            const int c0 = bn + wn + nt * 8 + tg * 2;
            #pragma unroll
            for (int ci = 0; ci < 4; ci++) {
                const int m = r0 + ((ci >> 1) ? 8 : 0);
                const int nn = c0 + (ci & 1);
                float v = acc[mt][nt][ci];
                if (bias) v += bias[nn];
                if (act == 1) {
                    v = (v >= 0.f) ? v : 0.01f * v;
                } else if (act == 2) {
                    float den = rnorm[m] * cnorm[nn];
                    v = (den != 0.f) ? v / den : 0.f;
                }
                C[(size_t)m * N + nn] = v;
            }
        }
    }
}

// ---------------- GRU step kernels v4: fragment-packed operands ----------------
// CTA: 64 rows x 32 gate-cols (x3 gates). grid (8, 32), 128 thr.
// A (h hi/lo) and B (Whh hi/lo) stored frag-packed in global; cp.async streams
// them chunk-by-chunk (GK=32), mainloop = LDS.128/LDS.64 + mma only.
// LAYER==1 bias contract: xin (g_xw1) ALREADY contains b_ih1+b_hh1 for r,z and
// b_ih1 for n; epilogue adds ONLY bhh_n. LAYER==0 adds all three bhh parts.
#define GM 64
#define GN 32
#define GK 32

#define SMA 2048            // floats per A buffer per array (4 mt x 4 kt x 32 x 4)
#define SMB 3072            // floats per B buffer per array (12 gt x 4 kt x 32 x 2)
#define OFF_AL (2 * SMA)
#define OFF_BH (4 * SMA)
#define OFF_BL (4 * SMA + 2 * SMB)
#define OFF_EX (4 * SMA + 4 * SMB)
#define SMG_FLT (OFF_EX + 96 + 96 + 32 * 3 * DF + GM * DF)

__device__ __forceinline__ void gru_load_chunk(
    float* sm, const float* __restrict__ hhi, const float* __restrict__ hlo,
    const float* __restrict__ whi, const float* __restrict__ wlo,
    int bm, int bn, int ch, int buf, int tid)
{
    const int mt0 = bm >> 4;
    const int gtb = bn >> 3;
    // A: 512 float4 per array
    #pragma unroll
    for (int j = 0; j < 4; j++) {
        int idx = tid + j * 128;
        int mt = idx >> 7, rem = idx & 127;
        int ktl = rem >> 5, ln = rem & 31;
        size_t g4 = (((size_t)(mt0 + mt) * 32 + (ch * 4 + ktl)) * 32 + ln) * 4;
        uint32_t d1 = (uint32_t)__cvta_generic_to_shared(sm + buf * SMA + idx * 4);
        CP_ASYNC16(d1, hhi + g4);
        uint32_t d2 = (uint32_t)__cvta_generic_to_shared(sm + OFF_AL + buf * SMA + idx * 4);
        CP_ASYNC16(d2, hlo + g4);
    }
    // B: 768 float4 per array
    #pragma unroll
    for (int j = 0; j < 6; j++) {
        int idx = tid + j * 128;
        int lgt = idx >> 6, rem = idx & 63;
        int ktl = rem >> 4, f4l = rem & 15;
        int gt = (lgt >> 2) * 32 + gtb + (lgt & 3);
        size_t g4 = (((size_t)gt * 32 + (ch * 4 + ktl)) * 16 + f4l) * 4;
        uint32_t d1 = (uint32_t)__cvta_generic_to_shared(sm + OFF_BH + buf * SMB + idx * 4);
        CP_ASYNC16(d1, whi + g4);
        uint32_t d2 = (uint32_t)__cvta_generic_to_shared(sm + OFF_BL + buf * SMB + idx * 4);
        CP_ASYNC16(d2, wlo + g4);
    }
    CP_COMMIT();
}

template<int LAYER>
__global__ void __launch_bounds__(128) gru_v4(
    const float* __restrict__ hin, const float* __restrict__ hin_hi,
    const float* __restrict__ hin_lo, float* __restrict__ hout,
    float* __restrict__ hout_hi, float* __restrict__ hout_lo,
    const float* __restrict__ whi, const float* __restrict__ wlo,
    const float* __restrict__ bhh, const float* __restrict__ xin,
    const float* __restrict__ Wih, const float* __restrict__ bih, int t)
{
    extern __shared__ float sm[];
    float* bih_s = sm + OFF_EX;         // [96] (layer0)
    float* bhh_s = bih_s + 96;          // [96]
    float* wih_s = bhh_s + 96;          // [32][3*DF] (layer0)
    float* xs    = wih_s + 32 * 3 * DF; // [64][DF] (layer0)

    const int tid = threadIdx.x;
    const int warp = tid >> 5, lane = tid & 31;
    const int wm = (warp & 1) * 32;          // 2 m-warps of 32 rows
    const int wn = (warp >> 1) * 16;         // 2 n-warps of 16 cols
    const int g = lane >> 2, tg = lane & 3;
    const int bn = blockIdx.x * GN;
    const int bm = blockIdx.y * GM;

    if (tid < 96) {
        const int gg = tid >> 5, c = tid & 31;
        bhh_s[tid] = bhh[gg * HID + bn + c];
        if (LAYER == 0) bih_s[tid] = bih[gg * HID + bn + c];
    }
    if (LAYER == 0) {
        for (int i = tid; i < 32 * 3 * DF; i += 128) {
            const int c = i / (3 * DF), r = i % (3 * DF);
            wih_s[i] = Wih[((r / DF) * HID + bn + c) * DF + (r % DF)];
        }
        for (int i = tid; i < GM * DF; i += 128) {
            const int r = i / DF, f = i % DF;
            xs[i] = xin[(bm + r) * (DF * TT) + f * TT + t];
        }
    }

    gru_load_chunk(sm, hin_hi, hin_lo, whi, wlo, bm, bn, 0, 0, tid);

    float acc[3][2][2][4];
    #pragma unroll
    for (int a = 0; a < 3; a++)
        #pragma unroll
        for (int b = 0; b < 2; b++)
            #pragma unroll
            for (int c = 0; c < 2; c++)
                #pragma unroll
                for (int d = 0; d < 4; d++) acc[a][b][c][d] = 0.f;

    const int mtl0 = wm >> 4;       // 0 or 2
    const int ntl0 = wn >> 3;       // 0 or 2

    #pragma unroll
    for (int ch = 0; ch < 8; ch++) {
        if (ch < 7) { gru_load_chunk(sm, hin_hi, hin_lo, whi, wlo, bm, bn, ch + 1, (ch + 1) & 1, tid); CP_WAIT1(); }
        else        { CP_WAIT0(); }
        __syncthreads();

        const float* Ah = sm + (ch & 1) * SMA;
        const float* Al = sm + OFF_AL + (ch & 1) * SMA;
        const float* Bh = sm + OFF_BH + (ch & 1) * SMB;
        const float* Bl = sm + OFF_BL + (ch & 1) * SMB;

        #pragma unroll
        for (int ks = 0; ks < 4; ks++) {
            uint32_t ah[2][4], al[2][4];
            #pragma unroll
            for (int mt = 0; mt < 2; mt++) {
                const int fo = (((mtl0 + mt) * 4 + ks) * 32 + lane) * 4;
                uint4 vh = *(const uint4*)(Ah + fo);
                uint4 vl = *(const uint4*)(Al + fo);
                ah[mt][0] = vh.x; ah[mt][1] = vh.y; ah[mt][2] = vh.z; ah[mt][3] = vh.w;
                al[mt][0] = vl.x; al[mt][1] = vl.y; al[mt][2] = vl.z; al[mt][3] = vl.w;
            }
            #pragma unroll
            for (int gg = 0; gg < 3; gg++) {
                #pragma unroll
                for (int nt = 0; nt < 2; nt++) {
                    const int lgt = gg * 4 + ntl0 + nt;
                    const int fo = (lgt * 4 + ks) * 64 + lane * 2;
                    uint2 vbh = *(const uint2*)(Bh + fo);
                    uint2 vbl = *(const uint2*)(Bl + fo);
                    uint32_t bh[2] = { vbh.x, vbh.y };
                    uint32_t bl[2] = { vbl.x, vbl.y };
                    #pragma unroll
                    for (int mt = 0; mt < 2; mt++) {
                        mma_tf32(acc[gg][mt][nt], al[mt], bh);
                        mma_tf32(acc[gg][mt][nt], ah[mt], bl);
                        mma_tf32(acc[gg][mt][nt], ah[mt], bh);
                    }
                }
            }
        }
        __syncthreads();
    }

    #pragma unroll
    for (int mt = 0; mt < 2; mt++) {
        #pragma unroll
        for (int nt = 0; nt < 2; nt++) {
            #pragma unroll
            for (int ci = 0; ci < 4; ci++) {
                const int rl = wm + mt * 16 + g + ((ci >> 1) ? 8 : 0);
                const int cl = wn + nt * 8 + tg * 2 + (ci & 1);
                const int row = bm + rl, col = bn + cl;
                float r, z, nn;
                if (LAYER == 0) {
                    float xr = bih_s[cl], xz = bih_s[32 + cl], xn = bih_s[64 + cl];
                    #pragma unroll
                    for (int f = 0; f < DF; f++) {
                        const float xv = xs[rl * DF + f];
                        xr += xv * wih_s[cl * 3 * DF + f];
                        xz += xv * wih_s[cl * 3 * DF + DF + f];
                        xn += xv * wih_s[cl * 3 * DF + 2 * DF + f];
                    }
                    r  = sigmoidf_(xr + acc[0][mt][nt][ci] + bhh_s[cl]);
                    z  = sigmoidf_(xz + acc[1][mt][nt][ci] + bhh_s[32 + cl]);
                    nn = tanhf(xn + r * (acc[2][mt][nt][ci] + bhh_s[64 + cl]));
                } else {
                    const size_t xb = ((size_t)row * TT + t) * G3 + col;
                    const float xr = xin[xb];
                    const float xz = xin[xb + HID];
                    const float xn = xin[xb + 2 * HID];
                    r  = sigmoidf_(xr + acc[0][mt][nt][ci]);
                    z  = sigmoidf_(xz + acc[1][mt][nt][ci]);
                    nn = tanhf(xn + r * (acc[2][mt][nt][ci] + bhh_s[64 + cl]));
                }
                const float ho = hin[(size_t)row * HID + col];
                const float hv = (1.f - z) * nn + z * ho;
                hout[(size_t)row * HID + col] = hv;
                uint32_t hi, lo; split_tf32(hv, hi, lo);
                const size_t pidx = hpack_idx(row, col);
                hout_hi[pidx] = __uint_as_float(hi);
                hout_lo[pidx] = __uint_as_float(lo);
                if (LAYER == 0) g_hs[((size_t)row * TT + t) * HID + col] = hv;
            }
        }
    }
}

// ---------------- small kernels ----------------
__global__ void split_mat_packed(const float* __restrict__ in, float* __restrict__ ohi,
                                 float* __restrict__ olo)
{
    const int i = blockIdx.x * 256 + threadIdx.x;
    if (i < G3 * HID) {
        const int gate = i >> 8, k = i & 255;
        uint32_t h, l;
        split_tf32(in[i], h, l);
        const size_t p = wpack_idx(gate, k);
        ohi[p] = __uint_as_float(h);
        olo[p] = __uint_as_float(l);
    }
}

__global__ void bias_combine(const float* __restrict__ bih, const float* __restrict__ bhh,
                             float* __restrict__ out)
{
    const int i = blockIdx.x * 256 + threadIdx.x;
    if (i < G3) out[i] = bih[i] + ((i < 512) ? bhh[i] : 0.f);
}

__global__ void mb_day_mean()
{
    const int b = blockIdx.x, h = threadIdx.x;
    float s = 0.f;
    for (int st = 0; st < 512; st++) s += g_mb[(b * 512 + st) * HID + h];
    g_mbday[b * HID + h] = s * (1.f / 512.f);
}

__global__ void day_topk(const float* __restrict__ thd)
{
    const int b = blockIdx.x;
    const int d = threadIdx.x;
    __shared__ float sim[NDAYS];
    const float* mbd = g_mbday + b * HID;
    float xn = 0.f;
    for (int i = 0; i < HID; i++) { float v = mbd[i]; xn += v * v; }
    xn = sqrtf(xn);
    if (d < NDAYS) {
        const float* yr = thd + d * HID;
        float yn = 0.f, dot = 0.f;
        for (int i = 0; i < HID; i++) { float y = yr[i]; yn += y * y; dot += mbd[i] * y; }
        const float den = xn * sqrtf(yn);
        sim[d] = (den != 0.f) ? dot / den : 0.f;
    }
    __syncthreads();
    if (d == 0) {
        for (int kk = 0; kk < KDAY; kk++) {
            float best = -1e30f; int bi = 0;
            for (int q = 0; q < NDAYS; q++)
                if (sim[q] > best) { best = sim[q]; bi = q; }
            g_dayidx[b * KDAY + kk] = bi;
            sim[bi] = -1e30f;
        }
    }
}

__global__ void make_rowmap()
{
    const int m = blockIdx.x * 256 + threadIdx.x;
    if (m < NSAMP) g_rowmap[m] = g_dayidx[m >> 9] * 512 + (m & 511);
}

__global__ void rownorm256(const float* __restrict__ X, float* __restrict__ out, int R)
{
    const int warp = (blockIdx.x * blockDim.x + threadIdx.x) >> 5;
    const int lane = threadIdx.x & 31;
    if (warp >= R) return;
    const float* r = X + (size_t)warp * HID;
    float s = 0.f;
    for (int i = lane; i < HID; i += 32) { float v = r[i]; s += v * v; }
    #pragma unroll
    for (int o = 16; o > 0; o >>= 1) s += __shfl_xor_sync(0xffffffffu, s, o);
    if (lane == 0) out[warp] = sqrtf(s);
}

__global__ void neigh_topk()
{
    const int n = blockIdx.x;
    const int tid = threadIdx.x;
    const float* row = g_cs + (size_t)n * NSAMP;

    float tv[NNB]; int ti[NNB];
    #pragma unroll
    for (int i = 0; i < NNB; i++) { tv[i] = -1e30f; ti[i] = 0x7fffffff; }

    for (int it = 0; it < NSAMP / 256; it++) {
        const int idx = tid + it * 256;
        const float v = row[idx];
        if (v > tv[NNB - 1]) {
            int p = NNB - 1;
            while (p > 0 && tv[p - 1] < v) { tv[p] = tv[p - 1]; ti[p] = ti[p - 1]; p--; }
            tv[p] = v; ti[p] = idx;
        }
    }

    __shared__ float sval[256 * NNB];
    __shared__ int   sidx[256 * NNB];
    __shared__ float rv[256];
    __shared__ int   rp[256];
    #pragma unroll
    for (int i = 0; i < NNB; i++) { sval[tid * NNB + i] = tv[i]; sidx[tid * NNB + i] = ti[i]; }
    __syncthreads();

    for (int kk = 0; kk < NNB; kk++) {
        float best = -1e30f; int bp = tid * NNB;
        #pragma unroll
        for (int i = 0; i < NNB; i++) {
            const float v = sval[tid * NNB + i];
            if (v > best) { best = v; bp = tid * NNB + i; }
        }
        rv[tid] = best; rp[tid] = bp;
        __syncthreads();
        for (int s = 128; s > 0; s >>= 1) {
            if (tid < s && rv[tid + s] > rv[tid]) { rv[tid] = rv[tid + s]; rp[tid] = rp[tid + s]; }
            __syncthreads();
        }
        if (tid == 0) {
            const int p = rp[0];
            g_vals[n * NNB + kk] = rv[0];
            g_nidx[n * NNB + kk] = sidx[p];
            sval[p] = -1e30f;
        }
        __syncthreads();
    }
}

__global__ void agg_fc(const float* __restrict__ fc_W, const float* __restrict__ fc_b,
                       float* __restrict__ y)
{
    const int n = blockIdx.x, h = threadIdx.x;
    float agg = 0.f;
    #pragma unroll
    for (int k = 0; k < NNB; k++) {
        const float v = g_vals[n * NNB + k] * (1.f / NNB);
        const int id = g_nidx[n * NNB + k];
        agg += v * g_kh[(size_t)id * HID + h];
    }
    float part = fc_W[h] * g_mb[n * HID + h] + fc_W[HID + h] * agg;
    __shared__ float red[256];
    red[h] = part;
    __syncthreads();
    for (int s = 128; s > 0; s >>= 1) {
        if (h < s) red[h] += red[h + s];
        __syncthreads();
    }
    if (h == 0) y[n] = red[0] + fc_b[0];
}

// ---------------- host ----------------
extern "C" void kernel_launch(void* const* d_in, const int* in_sizes, int n_in,
                              void* d_out, int out_size)
{
    const float* inp       = (const float*)d_in[0];
    const float* train_hid = (const float*)d_in[1];
    const float* thd       = (const float*)d_in[2];
    const float* W_ih0     = (const float*)d_in[3];
    const float* W_hh0     = (const float*)d_in[4];
    const float* b_ih0     = (const float*)d_in[5];
    const float* b_hh0     = (const float*)d_in[6];
    const float* W_ih1     = (const float*)d_in[7];
    const float* W_hh1     = (const float*)d_in[8];
    const float* b_ih1     = (const float*)d_in[9];
    const float* b_hh1     = (const float*)d_in[10];
    const float* lin0_W    = (const float*)d_in[11];
    const float* lin0_b    = (const float*)d_in[12];
    const float* lin1_W    = (const float*)d_in[13];
    const float* lin1_b    = (const float*)d_in[14];
    const float* lin2_W    = (const float*)d_in[15];
    const float* lin2_b    = (const float*)d_in[16];
    const float* proj1_W   = (const float*)d_in[17];
    const float* proj2_W   = (const float*)d_in[18];
    const float* fc_W      = (const float*)d_in[19];
    const float* fc_b      = (const float*)d_in[20];
    (void)in_sizes; (void)n_in; (void)out_size;

    float *p_h, *p_hhi, *p_hlo, *p_w0hi, *p_w0lo, *p_w1hi, *p_w1lo;
    float *p_hs, *p_xw1, *p_bias1, *p_mb1, *p_mb2, *p_mb, *p_kh, *p_khn, *p_q, *p_qn, *p_cs;
    int *p_rowmap;
    cudaGetSymbolAddress((void**)&p_h, g_h);
    cudaGetSymbolAddress((void**)&p_hhi, g_hhi);
    cudaGetSymbolAddress((void**)&p_hlo, g_hlo);
    cudaGetSymbolAddress((void**)&p_w0hi, g_w0hi);
    cudaGetSymbolAddress((void**)&p_w0lo, g_w0lo);
    cudaGetSymbolAddress((void**)&p_w1hi, g_w1hi);
    cudaGetSymbolAddress((void**)&p_w1lo, g_w1lo);
    cudaGetSymbolAddress((void**)&p_hs, g_hs);
    cudaGetSymbolAddress((void**)&p_xw1, g_xw1);
    cudaGetSymbolAddress((void**)&p_bias1, g_bias1);
    cudaGetSymbolAddress((void**)&p_mb1, g_mb1);
    cudaGetSymbolAddress((void**)&p_mb2, g_mb2);
    cudaGetSymbolAddress((void**)&p_mb, g_mb);
    cudaGetSymbolAddress((void**)&p_kh, g_kh);
    cudaGetSymbolAddress((void**)&p_khn, g_khn);
    cudaGetSymbolAddress((void**)&p_q, g_q);
    cudaGetSymbolAddress((void**)&p_qn, g_qn);
    cudaGetSymbolAddress((void**)&p_cs, g_cs);
    cudaGetSymbolAddress((void**)&p_rowmap, g_rowmap);

    const int smg = SMG_FLT * 4;
    cudaFuncSetAttribute(gru_v4<0>, cudaFuncAttributeMaxDynamicSharedMemorySize, smg);
    cudaFuncSetAttribute(gru_v4<1>, cudaFuncAttributeMaxDynamicSharedMemorySize, smg);

    const size_t HN = (size_t)BSZ * HID;
    const dim3 gru_grid(HID / GN, BSZ / GM);   // (8, 32)

    // ---- pre-split recurrent weights into frag-packed hi/lo ----
    split_mat_packed<<<(G3 * HID + 255) / 256, 256>>>(W_hh0, p_w0hi, p_w0lo);
    split_mat_packed<<<(G3 * HID + 255) / 256, 256>>>(W_hh1, p_w1hi, p_w1lo);

    // ---- GRU layer 0 ----
    cudaMemsetAsync(p_h, 0, HN * sizeof(float));
    cudaMemsetAsync(p_hhi, 0, HN * sizeof(float));
    cudaMemsetAsync(p_hlo, 0, HN * sizeof(float));
    for (int t = 0; t < TT; t++) {
        const int pr = t & 1, pw = pr ^ 1;
        gru_v4<0><<<gru_grid, 128, smg>>>(
            p_h + pr * HN, p_hhi + pr * HN, p_hlo + pr * HN,
            p_h + pw * HN, p_hhi + pw * HN, p_hlo + pw * HN,
            p_w0hi, p_w0lo, b_hh0, inp, W_ih0, b_ih0, t);
    }

    // ---- layer-1 input gates: one big 3xTF32 GEMM (combined bias) ----
    bias_combine<<<3, 256>>>(b_ih1, b_hh1, p_bias1);
    gemm_x<<<dim3(G3 / XBN, (BSZ * TT) / XBM), 256>>>(p_hs, W_ih1, p_bias1, p_xw1,
                                                      BSZ * TT, G3, HID, 0, nullptr, nullptr, nullptr);

    // ---- GRU layer 1 ----
    cudaMemsetAsync(p_h, 0, HN * sizeof(float));
    cudaMemsetAsync(p_hhi, 0, HN * sizeof(float));
    cudaMemsetAsync(p_hlo, 0, HN * sizeof(float));
    for (int t = 0; t < TT; t++) {
        const int pr = t & 1, pw = pr ^ 1;
        gru_v4<1><<<gru_grid, 128, smg>>>(
            p_h + pr * HN, p_hhi + pr * HN, p_hlo + pr * HN,
            p_h + pw * HN, p_hhi + pw * HN, p_hlo + pw * HN,
            p_w1hi, p_w1lo, b_hh1, p_xw1, nullptr, nullptr, t);
    }
    // t=59 writes parity 0 -> final h at p_h

    // ---- MLP (leaky relu) ----
    gemm_x<<<dim3(512 / XBN, BSZ / XBM), 256>>>(p_h, lin0_W, lin0_b, p_mb1,
                                                BSZ, 512, HID, 1, nullptr, nullptr, nullptr);
    gemm_x<<<dim3(512 / XBN, BSZ / XBM), 256>>>(p_mb1, lin1_W, lin1_b, p_mb2,
                                                BSZ, 512, 512, 1, nullptr, nullptr, nullptr);
    gemm_x<<<dim3(HID / XBN, BSZ / XBM), 256>>>(p_mb2, lin2_W, lin2_b, p_mb,
                                                BSZ, HID, 512, 1, nullptr, nullptr, nullptr);

    // ---- day similarity + gather ----
    mb_day_mean<<<4, HID>>>();
    day_topk<<<4, 256>>>(thd);
    make_rowmap<<<NSAMP / 256, 256>>>();
    gemm_x<<<dim3(HID / XBN, NSAMP / XBM), 256>>>(train_hid, proj2_W, nullptr, p_kh,
                                                  NSAMP, HID, HID, 0, p_rowmap, nullptr, nullptr);
    rownorm256<<<(NSAMP * 32) / 256, 256>>>(p_kh, p_khn, NSAMP);

    // ---- queries + cosine sim + neighbor aggregation ----
    gemm_x<<<dim3(HID / XBN, BSZ / XBM), 256>>>(p_mb, proj1_W, nullptr, p_q,
                                                BSZ, HID, HID, 0, nullptr, nullptr, nullptr);
    rownorm256<<<(BSZ * 32) / 256, 256>>>(p_q, p_qn, BSZ);
    gemm_x<<<dim3(NSAMP / XBN, BSZ / XBM), 256>>>(p_q, p_kh, nullptr, p_cs,
                                                  BSZ, NSAMP, HID, 2, nullptr, p_qn, p_khn);
    neigh_topk<<<BSZ, 256>>>();
    agg_fc<<<BSZ, 256>>>(fc_W, fc_b, (float*)d_out);
}

// round 12
// speedup vs baseline: 1.3951x; 1.0206x over previous
#include <cuda_runtime.h>
#include <cmath>
#include <cstdint>

#define BSZ   2048          // B_DAYS * STOCKS
#define TT    60
#define HID   256
#define G3    768           // 3*HID
#define DF    6
#define NSAMP 20480         // 4 * K_DAY * STOCKS
#define NDAYS 240
#define KDAY  10
#define NNB   10

// ---------------- device scratch (no allocations allowed) ----------------
__device__ float g_h[2 * BSZ * HID];          // ping-pong raw h (row-major)
__device__ float g_hhi[2 * BSZ * HID];        // ping-pong tf32-hi of h (FRAG-PACKED)
__device__ float g_hlo[2 * BSZ * HID];        // ping-pong tf32-lo of h (FRAG-PACKED)
__device__ float g_w0hi[G3 * HID];            // Whh0 hi (FRAG-PACKED)
__device__ float g_w0lo[G3 * HID];
__device__ float g_w1hi[G3 * HID];
__device__ float g_w1lo[G3 * HID];
__device__ float g_hs[BSZ * TT * HID];        // layer-0 hidden sequence
__device__ float g_xw1[(size_t)BSZ * TT * G3];// layer-1 input gates
__device__ float g_bias1[G3];
__device__ float g_mb1[BSZ * 512];
__device__ float g_mb2[BSZ * 512];
__device__ float g_mb[BSZ * HID];
__device__ float g_mbday[4 * HID];
__device__ int   g_dayidx[4 * KDAY];
__device__ int   g_rowmap[NSAMP];
__device__ float g_kh[NSAMP * HID];
__device__ float g_khn[NSAMP];
__device__ float g_q[BSZ * HID];
__device__ float g_qn[BSZ];
__device__ float g_cs[(size_t)BSZ * NSAMP];
__device__ float g_vals[BSZ * NNB];
__device__ int   g_nidx[BSZ * NNB];

// ---------------- tf32 helpers ----------------
__device__ __forceinline__ void split_tf32(float x, uint32_t& hi, uint32_t& lo)
{
    uint32_t h;
    asm("cvt.rna.tf32.f32 %0, %1;" : "=r"(h) : "f"(x));
    float rem = x - __uint_as_float(h);
    uint32_t l;
    asm("cvt.rna.tf32.f32 %0, %1;" : "=r"(l) : "f"(rem));
    hi = h; lo = l;
}

__device__ __forceinline__ void mma_tf32(float* d, const uint32_t* a, const uint32_t* b)
{
    asm volatile(
        "mma.sync.aligned.m16n8k8.row.col.f32.tf32.tf32.f32 "
        "{%0,%1,%2,%3}, {%4,%5,%6,%7}, {%8,%9}, {%0,%1,%2,%3};"
        : "+f"(d[0]), "+f"(d[1]), "+f"(d[2]), "+f"(d[3])
        : "r"(a[0]), "r"(a[1]), "r"(a[2]), "r"(a[3]), "r"(b[0]), "r"(b[1]));
}

__device__ __forceinline__ float sigmoidf_(float x) { return 1.f / (1.f + expf(-x)); }

#define CP_ASYNC16(dst, src) \
    asm volatile("cp.async.cg.shared.global [%0], [%1], 16;\n" :: "r"(dst), "l"(src))
#define CP_COMMIT()  asm volatile("cp.async.commit_group;\n")
#define CP_WAIT1()   asm volatile("cp.async.wait_group 1;\n")
#define CP_WAIT0()   asm volatile("cp.async.wait_group 0;\n")

// packed index helpers.
// A-frag pack (h): 16x8 tile -> [lane][word]: lane=(r%8)*4+(c%4), word=((r>>3)&1)+2*((c>>2)&1)
__device__ __forceinline__ size_t hpack_idx(int row, int col)
{
    return ((size_t)(row >> 4) * 32 + (col >> 3)) * 128
         + (((row & 7) << 2) + (col & 3)) * 4
         + ((row >> 3) & 1) + (((col >> 2) & 1) << 1);
}
// B-frag pack (W): 8(gate)x8(k) tile -> [lane][word]: lane=(gate%8)*4+(k%4), word=(k>>2)&1
__device__ __forceinline__ size_t wpack_idx(int gate, int k)
{
    return ((size_t)(gate >> 3) * 32 + (k >> 3)) * 64
         + (((gate & 7) << 2) + (k & 3)) * 2 + ((k >> 2) & 1);
}

// ---------------- 3xTF32 tensor-core GEMM: C[M,N] = A[M,K] @ B[N,K]^T + bias ----
// act: 0 none, 1 leaky(0.01), 2 cosine-normalize by rnorm[m]*cnorm[n]
#define XBM 128
#define XBN 64
#define XBK 32
#define XPAD 36

__global__ void gemm_x(const float* __restrict__ A, const float* __restrict__ B,
                       const float* __restrict__ bias, float* __restrict__ C,
                       int M, int N, int K, int act,
                       const int* __restrict__ rowmap,
                       const float* __restrict__ rnorm, const float* __restrict__ cnorm)
{
    __shared__ float As[XBM][XPAD];   // [m][k]
    __shared__ float Bs[XBN][XPAD];   // [n][k]
    const int bm = blockIdx.y * XBM;
    const int bn = blockIdx.x * XBN;
    const int tid = threadIdx.x;                 // 256
    const int warp = tid >> 5, lane = tid & 31;
    const int wm = (warp & 3) * 32;
    const int wn = (warp >> 2) * 32;
    const int g = lane >> 2, tg = lane & 3;

    float acc[2][4][4];
    #pragma unroll
    for (int a = 0; a < 2; a++)
        #pragma unroll
        for (int b = 0; b < 4; b++)
            #pragma unroll
            for (int c = 0; c < 4; c++) acc[a][b][c] = 0.f;

    for (int k0 = 0; k0 < K; k0 += XBK) {
        #pragma unroll
        for (int i = 0; i < 4; i++) {
            int idx = tid + i * 256;                   // 0..1023
            int r = idx >> 3, c4 = (idx & 7) * 4;
            int arow = bm + r;
            if (rowmap) arow = rowmap[arow];
            float4 v = *(const float4*)(A + (size_t)arow * K + k0 + c4);
            As[r][c4 + 0] = v.x; As[r][c4 + 1] = v.y;
            As[r][c4 + 2] = v.z; As[r][c4 + 3] = v.w;
        }
        #pragma unroll
        for (int i = 0; i < 2; i++) {
            int idx = tid + i * 256;                   // 0..511
            int r = idx >> 3, c4 = (idx & 7) * 4;
            float4 v = *(const float4*)(B + (size_t)(bn + r) * K + k0 + c4);
            Bs[r][c4 + 0] = v.x; Bs[r][c4 + 1] = v.y;
            Bs[r][c4 + 2] = v.z; Bs[r][c4 + 3] = v.w;
        }
        __syncthreads();
        #pragma unroll
        for (int kc = 0; kc < 4; kc++) {
            const int kb = kc * 8;
            uint32_t ahi[2][4], alo[2][4];
            #pragma unroll
            for (int mt = 0; mt < 2; mt++) {
                const int r0 = wm + mt * 16;
                split_tf32(As[r0 + g][kb + tg],         ahi[mt][0], alo[mt][0]);
                split_tf32(As[r0 + g + 8][kb + tg],     ahi[mt][1], alo[mt][1]);
                split_tf32(As[r0 + g][kb + tg + 4],     ahi[mt][2], alo[mt][2]);
                split_tf32(As[r0 + g + 8][kb + tg + 4], ahi[mt][3], alo[mt][3]);
            }
            uint32_t bhi[4][2], blo[4][2];
            #pragma unroll
            for (int nt = 0; nt < 4; nt++) {
                const int c0 = wn + nt * 8;
                split_tf32(Bs[c0 + g][kb + tg],     bhi[nt][0], blo[nt][0]);
                split_tf32(Bs[c0 + g][kb + tg + 4], bhi[nt][1], blo[nt][1]);
            }
            #pragma unroll
            for (int mt = 0; mt < 2; mt++)
                #pragma unroll
                for (int nt = 0; nt < 4; nt++) {
                    mma_tf32(acc[mt][nt], alo[mt], bhi[nt]);
                    mma_tf32(acc[mt][nt], ahi[mt], blo[nt]);
                    mma_tf32(acc[mt][nt], ahi[mt], bhi[nt]);
                }
        }
        __syncthreads();
    }

    #pragma unroll
    for (int mt = 0; mt < 2; mt++) {
        #pragma unroll
        for (int nt = 0; nt < 4; nt++) {
            const int r0 = bm + wm + mt * 16 + g;
            const int c0 = bn + wn + nt * 8 + tg * 2;
            #pragma unroll
            for (int ci = 0; ci < 4; ci++) {
                const int m = r0 + ((ci >> 1) ? 8 : 0);
                const int nn = c0 + (ci & 1);
                float v = acc[mt][nt][ci];
                if (bias) v += bias[nn];
                if (act == 1) {
                    v = (v >= 0.f) ? v : 0.01f * v;
                } else if (act == 2) {
                    float den = rnorm[m] * cnorm[nn];
                    v = (den != 0.f) ? v / den : 0.f;
                }
                C[(size_t)m * N + nn] = v;
            }
        }
    }
}

// ---------------- GRU step kernels v5: frag-packed operands, 256 threads ----------------
// CTA: 64 rows x 32 gate-cols (x3 gates). grid (8, 32), 256 thr = 8 warps (4m x 2n).
// A (h hi/lo) and B (Whh hi/lo) frag-packed in global; cp.async double-buffered chunks.
// LAYER==1 bias contract: xin (g_xw1) ALREADY contains b_ih1+b_hh1 for r,z and
// b_ih1 for n; epilogue adds ONLY bhh_n. LAYER==0 adds all three bhh parts.
#define GM 64
#define GN 32
#define GK 32

#define SMA 2048            // floats per A buffer per array (4 mt x 4 kt x 32 x 4)
#define SMB 3072            // floats per B buffer per array (12 gt x 4 kt x 32 x 2)
#define OFF_AL (2 * SMA)
#define OFF_BH (4 * SMA)
#define OFF_BL (4 * SMA + 2 * SMB)
#define OFF_EX (4 * SMA + 4 * SMB)
#define SMG_FLT (OFF_EX + 96 + 96 + 32 * 3 * DF + GM * DF)

__device__ __forceinline__ void gru_load_chunk(
    float* sm, const float* __restrict__ hhi, const float* __restrict__ hlo,
    const float* __restrict__ whi, const float* __restrict__ wlo,
    int bm, int bn, int ch, int buf, int tid)
{
    const int mt0 = bm >> 4;
    const int gtb = bn >> 3;
    // A: 512 float4 per array -> 2 iters of 256
    #pragma unroll
    for (int j = 0; j < 2; j++) {
        int idx = tid + j * 256;
        int mt = idx >> 7, rem = idx & 127;
        int ktl = rem >> 5, ln = rem & 31;
        size_t g4 = (((size_t)(mt0 + mt) * 32 + (ch * 4 + ktl)) * 32 + ln) * 4;
        uint32_t d1 = (uint32_t)__cvta_generic_to_shared(sm + buf * SMA + idx * 4);
        CP_ASYNC16(d1, hhi + g4);
        uint32_t d2 = (uint32_t)__cvta_generic_to_shared(sm + OFF_AL + buf * SMA + idx * 4);
        CP_ASYNC16(d2, hlo + g4);
    }
    // B: 768 float4 per array -> 3 iters of 256
    #pragma unroll
    for (int j = 0; j < 3; j++) {
        int idx = tid + j * 256;
        int lgt = idx >> 6, rem = idx & 63;
        int ktl = rem >> 4, f4l = rem & 15;
        int gt = (lgt >> 2) * 32 + gtb + (lgt & 3);
        size_t g4 = (((size_t)gt * 32 + (ch * 4 + ktl)) * 16 + f4l) * 4;
        uint32_t d1 = (uint32_t)__cvta_generic_to_shared(sm + OFF_BH + buf * SMB + idx * 4);
        CP_ASYNC16(d1, whi + g4);
        uint32_t d2 = (uint32_t)__cvta_generic_to_shared(sm + OFF_BL + buf * SMB + idx * 4);
        CP_ASYNC16(d2, wlo + g4);
    }
    CP_COMMIT();
}

template<int LAYER>
__global__ void __launch_bounds__(256) gru_v5(
    const float* __restrict__ hin, const float* __restrict__ hin_hi,
    const float* __restrict__ hin_lo, float* __restrict__ hout,
    float* __restrict__ hout_hi, float* __restrict__ hout_lo,
    const float* __restrict__ whi, const float* __restrict__ wlo,
    const float* __restrict__ bhh, const float* __restrict__ xin,
    const float* __restrict__ Wih, const float* __restrict__ bih, int t)
{
    extern __shared__ float sm[];
    float* bih_s = sm + OFF_EX;         // [96] (layer0)
    float* bhh_s = bih_s + 96;          // [96]
    float* wih_s = bhh_s + 96;          // [32][3*DF] (layer0)
    float* xs    = wih_s + 32 * 3 * DF; // [64][DF] (layer0)

    const int tid = threadIdx.x;
    const int warp = tid >> 5, lane = tid & 31;
    const int mw = warp & 3;                 // 4 m-warps of 16 rows
    const int nw = warp >> 2;                // 2 n-warps of 16 cols
    const int g = lane >> 2, tg = lane & 3;
    const int bn = blockIdx.x * GN;
    const int bm = blockIdx.y * GM;

    if (tid < 96) {
        const int gg = tid >> 5, c = tid & 31;
        bhh_s[tid] = bhh[gg * HID + bn + c];
        if (LAYER == 0) bih_s[tid] = bih[gg * HID + bn + c];
    }
    if (LAYER == 0) {
        for (int i = tid; i < 32 * 3 * DF; i += 256) {
            const int c = i / (3 * DF), r = i % (3 * DF);
            wih_s[i] = Wih[((r / DF) * HID + bn + c) * DF + (r % DF)];
        }
        for (int i = tid; i < GM * DF; i += 256) {
            const int r = i / DF, f = i % DF;
            xs[i] = xin[(bm + r) * (DF * TT) + f * TT + t];
        }
    }

    gru_load_chunk(sm, hin_hi, hin_lo, whi, wlo, bm, bn, 0, 0, tid);

    float acc[3][2][4];
    #pragma unroll
    for (int a = 0; a < 3; a++)
        #pragma unroll
        for (int b = 0; b < 2; b++)
            #pragma unroll
            for (int d = 0; d < 4; d++) acc[a][b][d] = 0.f;

    #pragma unroll
    for (int ch = 0; ch < 8; ch++) {
        if (ch < 7) { gru_load_chunk(sm, hin_hi, hin_lo, whi, wlo, bm, bn, ch + 1, (ch + 1) & 1, tid); CP_WAIT1(); }
        else        { CP_WAIT0(); }
        __syncthreads();

        const float* Ah = sm + (ch & 1) * SMA;
        const float* Al = sm + OFF_AL + (ch & 1) * SMA;
        const float* Bh = sm + OFF_BH + (ch & 1) * SMB;
        const float* Bl = sm + OFF_BL + (ch & 1) * SMB;

        #pragma unroll
        for (int ks = 0; ks < 4; ks++) {
            const int fa = ((mw * 4 + ks) * 32 + lane) * 4;
            uint4 vh = *(const uint4*)(Ah + fa);
            uint4 vl = *(const uint4*)(Al + fa);
            uint32_t ah[4] = { vh.x, vh.y, vh.z, vh.w };
            uint32_t al[4] = { vl.x, vl.y, vl.z, vl.w };
            #pragma unroll
            for (int gg = 0; gg < 3; gg++) {
                #pragma unroll
                for (int nt = 0; nt < 2; nt++) {
                    const int lgt = gg * 4 + nw * 2 + nt;
                    const int fo = (lgt * 4 + ks) * 64 + lane * 2;
                    uint2 vbh = *(const uint2*)(Bh + fo);
                    uint2 vbl = *(const uint2*)(Bl + fo);
                    uint32_t bh[2] = { vbh.x, vbh.y };
                    uint32_t bl[2] = { vbl.x, vbl.y };
                    mma_tf32(acc[gg][nt], al, bh);
                    mma_tf32(acc[gg][nt], ah, bl);
                    mma_tf32(acc[gg][nt], ah, bh);
                }
            }
        }
        __syncthreads();
    }

    #pragma unroll
    for (int nt = 0; nt < 2; nt++) {
        #pragma unroll
        for (int ci = 0; ci < 4; ci++) {
            const int rl = mw * 16 + g + ((ci >> 1) ? 8 : 0);
            const int cl = nw * 16 + nt * 8 + tg * 2 + (ci & 1);
            const int row = bm + rl, col = bn + cl;
            float r, z, nn;
            if (LAYER == 0) {
                float xr = bih_s[cl], xz = bih_s[32 + cl], xn = bih_s[64 + cl];
                #pragma unroll
                for (int f = 0; f < DF; f++) {
                    const float xv = xs[rl * DF + f];
                    xr += xv * wih_s[cl * 3 * DF + f];
                    xz += xv * wih_s[cl * 3 * DF + DF + f];
                    xn += xv * wih_s[cl * 3 * DF + 2 * DF + f];
                }
                r  = sigmoidf_(xr + acc[0][nt][ci] + bhh_s[cl]);
                z  = sigmoidf_(xz + acc[1][nt][ci] + bhh_s[32 + cl]);
                nn = tanhf(xn + r * (acc[2][nt][ci] + bhh_s[64 + cl]));
            } else {
                const size_t xb = ((size_t)row * TT + t) * G3 + col;
                const float xr = xin[xb];
                const float xz = xin[xb + HID];
                const float xn = xin[xb + 2 * HID];
                r  = sigmoidf_(xr + acc[0][nt][ci]);
                z  = sigmoidf_(xz + acc[1][nt][ci]);
                nn = tanhf(xn + r * (acc[2][nt][ci] + bhh_s[64 + cl]));
            }
            const float ho = hin[(size_t)row * HID + col];
            const float hv = (1.f - z) * nn + z * ho;
            hout[(size_t)row * HID + col] = hv;
            uint32_t hi, lo; split_tf32(hv, hi, lo);
            const size_t pidx = hpack_idx(row, col);
            hout_hi[pidx] = __uint_as_float(hi);
            hout_lo[pidx] = __uint_as_float(lo);
            if (LAYER == 0) g_hs[((size_t)row * TT + t) * HID + col] = hv;
        }
    }
}

// ---------------- small kernels ----------------
__global__ void split_mat_packed(const float* __restrict__ in, float* __restrict__ ohi,
                                 float* __restrict__ olo)
{
    const int i = blockIdx.x * 256 + threadIdx.x;
    if (i < G3 * HID) {
        const int gate = i >> 8, k = i & 255;
        uint32_t h, l;
        split_tf32(in[i], h, l);
        const size_t p = wpack_idx(gate, k);
        ohi[p] = __uint_as_float(h);
        olo[p] = __uint_as_float(l);
    }
}

__global__ void bias_combine(const float* __restrict__ bih, const float* __restrict__ bhh,
                             float* __restrict__ out)
{
    const int i = blockIdx.x * 256 + threadIdx.x;
    if (i < G3) out[i] = bih[i] + ((i < 512) ? bhh[i] : 0.f);
}

__global__ void mb_day_mean()
{
    const int b = blockIdx.x, h = threadIdx.x;
    float s = 0.f;
    for (int st = 0; st < 512; st++) s += g_mb[(b * 512 + st) * HID + h];
    g_mbday[b * HID + h] = s * (1.f / 512.f);
}

__global__ void day_topk(const float* __restrict__ thd)
{
    const int b = blockIdx.x;
    const int d = threadIdx.x;
    __shared__ float sim[NDAYS];
    const float* mbd = g_mbday + b * HID;
    float xn = 0.f;
    for (int i = 0; i < HID; i++) { float v = mbd[i]; xn += v * v; }
    xn = sqrtf(xn);
    if (d < NDAYS) {
        const float* yr = thd + d * HID;
        float yn = 0.f, dot = 0.f;
        for (int i = 0; i < HID; i++) { float y = yr[i]; yn += y * y; dot += mbd[i] * y; }
        const float den = xn * sqrtf(yn);
        sim[d] = (den != 0.f) ? dot / den : 0.f;
    }
    __syncthreads();
    if (d == 0) {
        for (int kk = 0; kk < KDAY; kk++) {
            float best = -1e30f; int bi = 0;
            for (int q = 0; q < NDAYS; q++)
                if (sim[q] > best) { best = sim[q]; bi = q; }
            g_dayidx[b * KDAY + kk] = bi;
            sim[bi] = -1e30f;
        }
    }
}

__global__ void make_rowmap()
{
    const int m = blockIdx.x * 256 + threadIdx.x;
    if (m < NSAMP) g_rowmap[m] = g_dayidx[m >> 9] * 512 + (m & 511);
}

__global__ void rownorm256(const float* __restrict__ X, float* __restrict__ out, int R)
{
    const int warp = (blockIdx.x * blockDim.x + threadIdx.x) >> 5;
    const int lane = threadIdx.x & 31;
    if (warp >= R) return;
    const float* r = X + (size_t)warp * HID;
    float s = 0.f;
    for (int i = lane; i < HID; i += 32) { float v = r[i]; s += v * v; }
    #pragma unroll
    for (int o = 16; o > 0; o >>= 1) s += __shfl_xor_sync(0xffffffffu, s, o);
    if (lane == 0) out[warp] = sqrtf(s);
}

__global__ void neigh_topk()
{
    const int n = blockIdx.x;
    const int tid = threadIdx.x;
    const float* row = g_cs + (size_t)n * NSAMP;

    float tv[NNB]; int ti[NNB];
    #pragma unroll
    for (int i = 0; i < NNB; i++) { tv[i] = -1e30f; ti[i] = 0x7fffffff; }

    for (int it = 0; it < NSAMP / 256; it++) {
        const int idx = tid + it * 256;
        const float v = row[idx];
        if (v > tv[NNB - 1]) {
            int p = NNB - 1;
            while (p > 0 && tv[p - 1] < v) { tv[p] = tv[p - 1]; ti[p] = ti[p - 1]; p--; }
            tv[p] = v; ti[p] = idx;
        }
    }

    __shared__ float sval[256 * NNB];
    __shared__ int   sidx[256 * NNB];
    __shared__ float rv[256];
    __shared__ int   rp[256];
    #pragma unroll
    for (int i = 0; i < NNB; i++) { sval[tid * NNB + i] = tv[i]; sidx[tid * NNB + i] = ti[i]; }
    __syncthreads();

    for (int kk = 0; kk < NNB; kk++) {
        float best = -1e30f; int bp = tid * NNB;
        #pragma unroll
        for (int i = 0; i < NNB; i++) {
            const float v = sval[tid * NNB + i];
            if (v > best) { best = v; bp = tid * NNB + i; }
        }
        rv[tid] = best; rp[tid] = bp;
        __syncthreads();
        for (int s = 128; s > 0; s >>= 1) {
            if (tid < s && rv[tid + s] > rv[tid]) { rv[tid] = rv[tid + s]; rp[tid] = rp[tid + s]; }
            __syncthreads();
        }
        if (tid == 0) {
            const int p = rp[0];
            g_vals[n * NNB + kk] = rv[0];
            g_nidx[n * NNB + kk] = sidx[p];
            sval[p] = -1e30f;
        }
        __syncthreads();
    }
}

__global__ void agg_fc(const float* __restrict__ fc_W, const float* __restrict__ fc_b,
                       float* __restrict__ y)
{
    const int n = blockIdx.x, h = threadIdx.x;
    float agg = 0.f;
    #pragma unroll
    for (int k = 0; k < NNB; k++) {
        const float v = g_vals[n * NNB + k] * (1.f / NNB);
        const int id = g_nidx[n * NNB + k];
        agg += v * g_kh[(size_t)id * HID + h];
    }
    float part = fc_W[h] * g_mb[n * HID + h] + fc_W[HID + h] * agg;
    __shared__ float red[256];
    red[h] = part;
    __syncthreads();
    for (int s = 128; s > 0; s >>= 1) {
        if (h < s) red[h] += red[h + s];
        __syncthreads();
    }
    if (h == 0) y[n] = red[0] + fc_b[0];
}

// ---------------- host ----------------
extern "C" void kernel_launch(void* const* d_in, const int* in_sizes, int n_in,
                              void* d_out, int out_size)
{
    const float* inp       = (const float*)d_in[0];
    const float* train_hid = (const float*)d_in[1];
    const float* thd       = (const float*)d_in[2];
    const float* W_ih0     = (const float*)d_in[3];
    const float* W_hh0     = (const float*)d_in[4];
    const float* b_ih0     = (const float*)d_in[5];
    const float* b_hh0     = (const float*)d_in[6];
    const float* W_ih1     = (const float*)d_in[7];
    const float* W_hh1     = (const float*)d_in[8];
    const float* b_ih1     = (const float*)d_in[9];
    const float* b_hh1     = (const float*)d_in[10];
    const float* lin0_W    = (const float*)d_in[11];
    const float* lin0_b    = (const float*)d_in[12];
    const float* lin1_W    = (const float*)d_in[13];
    const float* lin1_b    = (const float*)d_in[14];
    const float* lin2_W    = (const float*)d_in[15];
    const float* lin2_b    = (const float*)d_in[16];
    const float* proj1_W   = (const float*)d_in[17];
    const float* proj2_W   = (const float*)d_in[18];
    const float* fc_W      = (const float*)d_in[19];
    const float* fc_b      = (const float*)d_in[20];
    (void)in_sizes; (void)n_in; (void)out_size;

    float *p_h, *p_hhi, *p_hlo, *p_w0hi, *p_w0lo, *p_w1hi, *p_w1lo;
    float *p_hs, *p_xw1, *p_bias1, *p_mb1, *p_mb2, *p_mb, *p_kh, *p_khn, *p_q, *p_qn, *p_cs;
    int *p_rowmap;
    cudaGetSymbolAddress((void**)&p_h, g_h);
    cudaGetSymbolAddress((void**)&p_hhi, g_hhi);
    cudaGetSymbolAddress((void**)&p_hlo, g_hlo);
    cudaGetSymbolAddress((void**)&p_w0hi, g_w0hi);
    cudaGetSymbolAddress((void**)&p_w0lo, g_w0lo);
    cudaGetSymbolAddress((void**)&p_w1hi, g_w1hi);
    cudaGetSymbolAddress((void**)&p_w1lo, g_w1lo);
    cudaGetSymbolAddress((void**)&p_hs, g_hs);
    cudaGetSymbolAddress((void**)&p_xw1, g_xw1);
    cudaGetSymbolAddress((void**)&p_bias1, g_bias1);
    cudaGetSymbolAddress((void**)&p_mb1, g_mb1);
    cudaGetSymbolAddress((void**)&p_mb2, g_mb2);
    cudaGetSymbolAddress((void**)&p_mb, g_mb);
    cudaGetSymbolAddress((void**)&p_kh, g_kh);
    cudaGetSymbolAddress((void**)&p_khn, g_khn);
    cudaGetSymbolAddress((void**)&p_q, g_q);
    cudaGetSymbolAddress((void**)&p_qn, g_qn);
    cudaGetSymbolAddress((void**)&p_cs, g_cs);
    cudaGetSymbolAddress((void**)&p_rowmap, g_rowmap);

    const int smg = SMG_FLT * 4;
    cudaFuncSetAttribute(gru_v5<0>, cudaFuncAttributeMaxDynamicSharedMemorySize, smg);
    cudaFuncSetAttribute(gru_v5<1>, cudaFuncAttributeMaxDynamicSharedMemorySize, smg);

    const size_t HN = (size_t)BSZ * HID;
    const dim3 gru_grid(HID / GN, BSZ / GM);   // (8, 32)

    // ---- pre-split recurrent weights into frag-packed hi/lo ----
    split_mat_packed<<<(G3 * HID + 255) / 256, 256>>>(W_hh0, p_w0hi, p_w0lo);
    split_mat_packed<<<(G3 * HID + 255) / 256, 256>>>(W_hh1, p_w1hi, p_w1lo);

    // ---- GRU layer 0 ----
    cudaMemsetAsync(p_h, 0, HN * sizeof(float));
    cudaMemsetAsync(p_hhi, 0, HN * sizeof(float));
    cudaMemsetAsync(p_hlo, 0, HN * sizeof(float));
    for (int t = 0; t < TT; t++) {
        const int pr = t & 1, pw = pr ^ 1;
        gru_v5<0><<<gru_grid, 256, smg>>>(
            p_h + pr * HN, p_hhi + pr * HN, p_hlo + pr * HN,
            p_h + pw * HN, p_hhi + pw * HN, p_hlo + pw * HN,
            p_w0hi, p_w0lo, b_hh0, inp, W_ih0, b_ih0, t);
    }

    // ---- layer-1 input gates: one big 3xTF32 GEMM (combined bias) ----
    bias_combine<<<3, 256>>>(b_ih1, b_hh1, p_bias1);
    gemm_x<<<dim3(G3 / XBN, (BSZ * TT) / XBM), 256>>>(p_hs, W_ih1, p_bias1, p_xw1,
                                                      BSZ * TT, G3, HID, 0, nullptr, nullptr, nullptr);

    // ---- GRU layer 1 ----
    cudaMemsetAsync(p_h, 0, HN * sizeof(float));
    cudaMemsetAsync(p_hhi, 0, HN * sizeof(float));
    cudaMemsetAsync(p_hlo, 0, HN * sizeof(float));
    for (int t = 0; t < TT; t++) {
        const int pr = t & 1, pw = pr ^ 1;
        gru_v5<1><<<gru_grid, 256, smg>>>(
            p_h + pr * HN, p_hhi + pr * HN, p_hlo + pr * HN,
            p_h + pw * HN, p_hhi + pw * HN, p_hlo + pw * HN,
            p_w1hi, p_w1lo, b_hh1, p_xw1, nullptr, nullptr, t);
    }
    // t=59 writes parity 0 -> final h at p_h

    // ---- MLP (leaky relu) ----
    gemm_x<<<dim3(512 / XBN, BSZ / XBM), 256>>>(p_h, lin0_W, lin0_b, p_mb1,
                                                BSZ, 512, HID, 1, nullptr, nullptr, nullptr);
    gemm_x<<<dim3(512 / XBN, BSZ / XBM), 256>>>(p_mb1, lin1_W, lin1_b, p_mb2,
                                                BSZ, 512, 512, 1, nullptr, nullptr, nullptr);
    gemm_x<<<dim3(HID / XBN, BSZ / XBM), 256>>>(p_mb2, lin2_W, lin2_b, p_mb,
                                                BSZ, HID, 512, 1, nullptr, nullptr, nullptr);

    // ---- day similarity + gather ----
    mb_day_mean<<<4, HID>>>();
    day_topk<<<4, 256>>>(thd);
    make_rowmap<<<NSAMP / 256, 256>>>();
    gemm_x<<<dim3(HID / XBN, NSAMP / XBM), 256>>>(train_hid, proj2_W, nullptr, p_kh,
                                                  NSAMP, HID, HID, 0, p_rowmap, nullptr, nullptr);
    rownorm256<<<(NSAMP * 32) / 256, 256>>>(p_kh, p_khn, NSAMP);

    // ---- queries + cosine sim + neighbor aggregation ----
    gemm_x<<<dim3(HID / XBN, BSZ / XBM), 256>>>(p_mb, proj1_W, nullptr, p_q,
                                                BSZ, HID, HID, 0, nullptr, nullptr, nullptr);
    rownorm256<<<(BSZ * 32) / 256, 256>>>(p_q, p_qn, BSZ);
    gemm_x<<<dim3(NSAMP / XBN, BSZ / XBM), 256>>>(p_q, p_kh, nullptr, p_cs,
                                                  BSZ, NSAMP, HID, 2, nullptr, p_qn, p_khn);
    neigh_topk<<<BSZ, 256>>>();
    agg_fc<<<BSZ, 256>>>(fc_W, fc_b, (float*)d_out);
}